// round 12
// baseline (speedup 1.0000x reference)
#include <cuda_runtime.h>
#include <cuda_bf16.h>
#include <cstdint>

#define NB 4
#define NT 2048
#define ND 1024
#define NH 16
#define NHD 64
#define NM (NB*NT)   // 8192 rows

// Scratch (allocation-free rule: __device__ globals).
__device__ float g_q [NB*NH*NT*NHD];   // [B,H,T,HD]
__device__ float g_kt[NB*NH*NHD*NT];   // [B,H,HD,T]  (K projected + transposed)
__device__ float g_v [NB*NH*NT*NHD];   // [B,H,T,HD]
__device__ float g_o [NB*NH*NT*NHD];   // [B,H,T,HD] attention output

__device__ __forceinline__ unsigned f2tf(float f) {
    unsigned u;
    asm("cvt.rna.tf32.f32 %0, %1;" : "=r"(u) : "f"(f));
    return u;
}

__device__ __forceinline__ void mma_tf32(float c[4], const unsigned a[4], const unsigned b[2]) {
    asm volatile(
        "mma.sync.aligned.m16n8k8.row.col.f32.tf32.tf32.f32 "
        "{%0,%1,%2,%3}, {%4,%5,%6,%7}, {%8,%9}, {%0,%1,%2,%3};"
        : "+f"(c[0]), "+f"(c[1]), "+f"(c[2]), "+f"(c[3])
        : "r"(a[0]), "r"(a[1]), "r"(a[2]), "r"(a[3]), "r"(b[0]), "r"(b[1]));
}

// bf16 m16n8k16 mma, fp32 accumulate.
__device__ __forceinline__ void mma_bf16(float c[4], const unsigned a[4],
                                         unsigned b0, unsigned b1) {
    asm volatile(
        "mma.sync.aligned.m16n8k16.row.col.f32.bf16.bf16.f32 "
        "{%0,%1,%2,%3}, {%4,%5,%6,%7}, {%8,%9}, {%0,%1,%2,%3};"
        : "+f"(c[0]), "+f"(c[1]), "+f"(c[2]), "+f"(c[3])
        : "r"(a[0]), "r"(a[1]), "r"(a[2]), "r"(a[3]), "r"(b0), "r"(b1));
}

__device__ __forceinline__ unsigned pack_bf2(float a, float b) {
    __nv_bfloat162 t = __floats2bfloat162_rn(a, b);   // low = a, high = b
    return *reinterpret_cast<unsigned*>(&t);
}
__device__ __forceinline__ float bfr(float a) {
    return __bfloat162float(__float2bfloat16_rn(a));
}

// ---------------------------------------------------------------------------
// Tensor-core tf32 GEMM (verbatim from passing R3/R5-R8): C = A@W^T + bias.
// ---------------------------------------------------------------------------
template<int AMODE, int OMODE>
__global__ __launch_bounds__(256)
void gemm_tc(const float* __restrict__ A, const float* __restrict__ W,
             const float* __restrict__ bias, float* __restrict__ Cout)
{
    extern __shared__ unsigned sh[];
    unsigned* As = sh;           // 2 bufs x 4096 u32
    unsigned* Ws = sh + 8192;

    const int tid  = threadIdx.x;
    const int lane = tid & 31;
    const int warp = tid >> 5;
    const int wm   = warp & 1;
    const int wn   = warp >> 1;
    const int bm   = blockIdx.y * 128;
    const int bn   = blockIdx.x * 128;

    float acc[4][4][4];
#pragma unroll
    for (int mi = 0; mi < 4; mi++)
#pragma unroll
        for (int nj = 0; nj < 4; nj++)
#pragma unroll
            for (int r = 0; r < 4; r++) acc[mi][nj][r] = 0.f;

    float4 ar[4], wr[4];

    auto ldg = [&](int s) {
#pragma unroll
        for (int l = 0; l < 4; l++) {
            int idx = l * 256 + tid;
            int row = idx >> 3;
            int kq  = idx & 7;
            int kg  = s * 32 + kq * 4;
            if (AMODE == 0) {
                ar[l] = *(const float4*)(A + (size_t)(bm + row) * ND + kg);
            } else {
                int m  = bm + row;
                int b_ = m >> 11, t_ = m & (NT - 1);
                int h_ = kg >> 6, hd = kg & 63;
                ar[l] = *(const float4*)(A + (((size_t)(b_ * NH + h_) * NT + t_) * NHD + hd));
            }
            wr[l] = *(const float4*)(W + (size_t)(bn + row) * ND + kg);
        }
    };

    auto sts = [&](int buf) {
        unsigned* ab = As + buf * 4096;
        unsigned* wb = Ws + buf * 4096;
#pragma unroll
        for (int l = 0; l < 4; l++) {
            int idx = l * 256 + tid;
            int row = idx >> 3;
            int kq  = idx & 7;
            {
                unsigned* p = ab + (((row >> 4) * 4 + (kq >> 1)) << 7);
                int reg = ((kq & 1) << 1) + ((row >> 3) & 1);
                int lb  = (row & 7) * 4;
                p[(lb + 0) * 4 + reg] = f2tf(ar[l].x);
                p[(lb + 1) * 4 + reg] = f2tf(ar[l].y);
                p[(lb + 2) * 4 + reg] = f2tf(ar[l].z);
                p[(lb + 3) * 4 + reg] = f2tf(ar[l].w);
            }
            {
                unsigned* p = wb + (((row >> 3) * 4 + (kq >> 1)) << 6);
                int reg = (kq & 1);
                int lb  = (row & 7) * 4;
                p[(lb + 0) * 2 + reg] = f2tf(wr[l].x);
                p[(lb + 1) * 2 + reg] = f2tf(wr[l].y);
                p[(lb + 2) * 2 + reg] = f2tf(wr[l].z);
                p[(lb + 3) * 2 + reg] = f2tf(wr[l].w);
            }
        }
    };

    auto compute = [&](int buf) {
        const unsigned* ab = As + buf * 4096;
        const unsigned* wb = Ws + buf * 4096;
#pragma unroll
        for (int kt = 0; kt < 4; kt++) {
            unsigned af[4][4];
#pragma unroll
            for (int mi = 0; mi < 4; mi++) {
                uint4 t = *(const uint4*)(ab + ((((wm * 4 + mi) * 4 + kt)) << 7) + (lane << 2));
                af[mi][0] = t.x; af[mi][1] = t.y; af[mi][2] = t.z; af[mi][3] = t.w;
            }
            unsigned bf[4][2];
#pragma unroll
            for (int nj = 0; nj < 4; nj++) {
                uint2 t = *(const uint2*)(wb + ((((wn * 4 + nj) * 4 + kt)) << 6) + (lane << 1));
                bf[nj][0] = t.x; bf[nj][1] = t.y;
            }
#pragma unroll
            for (int mi = 0; mi < 4; mi++)
#pragma unroll
                for (int nj = 0; nj < 4; nj++)
                    mma_tf32(acc[mi][nj], af[mi], bf[nj]);
        }
    };

    ldg(0);
    sts(0);
    __syncthreads();
    for (int s = 0; s < 32; s++) {
        int buf = s & 1;
        if (s < 31) ldg(s + 1);
        compute(buf);
        if (s < 31) sts(buf ^ 1);
        __syncthreads();
    }

#pragma unroll
    for (int nj = 0; nj < 4; nj++) {
        int col = bn + (wn * 4 + nj) * 8 + (lane & 3) * 2;
        float b0 = bias[col], b1 = bias[col + 1];
#pragma unroll
        for (int mi = 0; mi < 4; mi++) {
            int row = bm + (wm * 4 + mi) * 16 + (lane >> 2);
            float v00 = acc[mi][nj][0] + b0, v01 = acc[mi][nj][1] + b1;
            float v10 = acc[mi][nj][2] + b0, v11 = acc[mi][nj][3] + b1;
            if (OMODE == 2) {
                *(float2*)(Cout + (size_t)row * ND + col)       = make_float2(v00, v01);
                *(float2*)(Cout + (size_t)(row + 8) * ND + col) = make_float2(v10, v11);
            } else if (OMODE == 0) {
                int b_ = row >> 11, t_ = row & (NT - 1);
                int h_ = col >> 6, hd = col & 63;
                float* p = Cout + (((size_t)(b_ * NH + h_) * NT + t_) * NHD + hd);
                *(float2*)p             = make_float2(v00, v01);
                *(float2*)(p + 8 * NHD) = make_float2(v10, v11);
            } else { // OMODE 1: [B,H,HD,T]
                int b_ = row >> 11, t_ = row & (NT - 1);
                int h_ = col >> 6, hd = col & 63;
                float* p = Cout + (((size_t)(b_ * NH + h_) * NHD + hd) * NT + t_);
                p[0]      = v00;
                p[NT]     = v01;
                p[8]      = v10;
                p[NT + 8] = v11;
            }
        }
    }
}

// ---------------------------------------------------------------------------
// Flash attention v7: bf16 hi/lo on mma.m16n8k16 with COMPENSATED P.
// 256 threads = 8 warps; CTA = 128 queries; warp owns 16 rows (mt = warp).
// S  = qh*kh + qh*kl + ql*kh   (residual ~2^-18)
// PV = ph*vh + ph*vl + pl*vh   (p = ph + pl split in registers, ~2^-17)
// Row-sum l accumulates the fp32 p directly (exact normalization).
// P C-frag -> A-frag is a pure register repack (no shuffles) for k16.
//
// smem (u32), 64 KB total -> 2 CTAs/SM:
//  QH [0,4096)     tile(mt0..7, kt0..3): uint4/lane = A-frag (bf16x2 pairs)
//  QL [4096,8192)
//  KB [8192,12288) tile(nt0..7, kt0..3): uint4/lane = (hi b0, hi b1, lo b0, lo b1)
//  VB [12288,16384) same structure for V
// ---------------------------------------------------------------------------
__global__ __launch_bounds__(256, 2)
void attn_mma(const float* __restrict__ qp, const float* __restrict__ ktp,
              const float* __restrict__ vp, float* __restrict__ ao)
{
    extern __shared__ unsigned smu[];

    const int tid  = threadIdx.x;
    const int lane = tid & 31;
    const int warp = tid >> 5;
    const int r    = lane >> 2;          // 0..7
    const int g    = lane & 3;           // 0..3
    const int bh   = blockIdx.y;
    const int q0   = blockIdx.x * 128;

    const float* qb = qp  + ((size_t)bh * NT + q0) * NHD;
    const float* kb = ktp + (size_t)bh * NHD * NT;
    const float* vb = vp  + (size_t)bh * NT * NHD;

    // ---- Stage Q once in bf16 A-frag order (hi/lo). 2048 float4. ----
#pragma unroll
    for (int i = 0; i < 8; i++) {
        int idx = i * 256 + tid;
        int uu = idx & 31, blk = idx >> 5;
        int qrow = (uu >> 2) + (blk & 15) * 8;      // 0..127
        int f4   = (uu & 3) + (blk >> 4) * 4;       // 0..15
        float4 x = *(const float4*)(qb + qrow * NHD + f4 * 4);
        int mt = qrow >> 4;
        int kt = f4 >> 2;
        int base8 = (f4 & 3) * 4;                   // h16 of first element
        int colbit = base8 >> 3;
        int gg = (base8 & 7) >> 1;                  // 0 or 2
        int reg = ((qrow >> 3) & 1) | (colbit << 1);
        int a1 = (mt * 4 + kt) * 128 + ((qrow & 7) * 4 + gg) * 4 + reg;
        int a2 = a1 + 4;                            // gg+1
        smu[a1]        = pack_bf2(x.x, x.y);
        smu[4096 + a1] = pack_bf2(x.x - bfr(x.x), x.y - bfr(x.y));
        smu[a2]        = pack_bf2(x.z, x.w);
        smu[4096 + a2] = pack_bf2(x.z - bfr(x.z), x.w - bfr(x.w));
    }

    float o[8][4];
#pragma unroll
    for (int nt = 0; nt < 8; nt++)
#pragma unroll
        for (int c = 0; c < 4; c++) o[nt][c] = 0.f;
    float m0 = -1e30f, m1 = -1e30f, l0 = 0.f, l1 = 0.f;

    for (int t0 = 0; t0 < NT; t0 += 64) {
        __syncthreads();   // prev compute done before restaging (covers Q on iter 0)

        // ---- Stage K: pack hd-pairs (contraction dim) into bf16x2 hi/lo. ----
#pragma unroll
        for (int i = 0; i < 2; i++) {
            int idx = i * 256 + tid;
            int hp  = idx & 31;          // hd pair: hd = 2hp, 2hp+1
            int kf4 = idx >> 5;          // key float4: keys kf4*4..+3
            const float* kr = kb + (size_t)(2 * hp) * NT + t0 + kf4 * 4;
            float4 x0 = *(const float4*)kr;
            float4 x1 = *(const float4*)(kr + NT);
            float e0[4] = {x0.x, x0.y, x0.z, x0.w};
            float e1[4] = {x1.x, x1.y, x1.z, x1.w};
            int kt = hp >> 3, gK = hp & 3, regb = (hp >> 2) & 1;
            int rot = hp >> 3;
#pragma unroll
            for (int j = 0; j < 4; j++) {
                int jj = (j + rot) & 3;
                int key = kf4 * 4 + jj;
                int ad = 8192 + (((key >> 3) * 4 + kt) * 128)
                         + ((key & 7) * 4 + gK) * 4 + regb;
                float ka = e0[jj], kc = e1[jj];
                smu[ad]     = pack_bf2(ka, kc);
                smu[ad + 2] = pack_bf2(ka - bfr(ka), kc - bfr(kc));
            }
        }
        // ---- Stage V: pack key-pairs (contraction dim) into bf16x2 hi/lo. ----
#pragma unroll
        for (int i = 0; i < 2; i++) {
            int idx = i * 256 + tid;
            int kp  = idx & 31;          // key pair: keys 2kp, 2kp+1
            int hf4 = idx >> 5;          // hd float4
            const float* vr = vb + (size_t)(t0 + 2 * kp) * NHD + hf4 * 4;
            float4 y0 = *(const float4*)vr;
            float4 y1 = *(const float4*)(vr + NHD);
            float e0[4] = {y0.x, y0.y, y0.z, y0.w};
            float e1[4] = {y1.x, y1.y, y1.z, y1.w};
            int kt = kp >> 3, gV = kp & 3, regb = (kp >> 2) & 1;
            int rot = kp >> 3;
#pragma unroll
            for (int e = 0; e < 4; e++) {
                int ee = (e + rot) & 3;
                int hd = hf4 * 4 + ee;
                int ad = 12288 + (((hd >> 3) * 4 + kt) * 128)
                         + ((hd & 7) * 4 + gV) * 4 + regb;
                float va = e0[ee], vc = e1[ee];
                smu[ad]     = pack_bf2(va, vc);
                smu[ad + 2] = pack_bf2(va - bfr(va), vc - bfr(vc));
            }
        }
        __syncthreads();

        // ---- S = Q K^T : 4 k16-tiles, 3 chains ----
        float s[8][4];
#pragma unroll
        for (int nt = 0; nt < 8; nt++)
#pragma unroll
            for (int c = 0; c < 4; c++) s[nt][c] = 0.f;

#pragma unroll
        for (int kt = 0; kt < 4; kt++) {
            uint4 qh4 = *(const uint4*)(smu + (warp * 4 + kt) * 128 + lane * 4);
            uint4 ql4 = *(const uint4*)(smu + 4096 + (warp * 4 + kt) * 128 + lane * 4);
            unsigned ah[4] = {qh4.x, qh4.y, qh4.z, qh4.w};
            unsigned al[4] = {ql4.x, ql4.y, ql4.z, ql4.w};
#pragma unroll
            for (int half = 0; half < 2; half++) {
                uint4 kk[4];
#pragma unroll
                for (int j = 0; j < 4; j++)
                    kk[j] = *(const uint4*)(smu + 8192
                              + (((half * 4 + j) * 4 + kt) * 128) + lane * 4);
#pragma unroll
                for (int j = 0; j < 4; j++)
                    mma_bf16(s[half*4+j], ah, kk[j].x, kk[j].y);   // qh*kh
#pragma unroll
                for (int j = 0; j < 4; j++)
                    mma_bf16(s[half*4+j], ah, kk[j].z, kk[j].w);   // qh*kl
#pragma unroll
                for (int j = 0; j < 4; j++)
                    mma_bf16(s[half*4+j], al, kk[j].x, kk[j].y);   // ql*kh
            }
        }

        // ---- online softmax (rows r, r+8; quad-wide reductions) ----
        float mx0 = -1e30f, mx1 = -1e30f;
#pragma unroll
        for (int nt = 0; nt < 8; nt++) {
            s[nt][0] *= 0.125f; s[nt][1] *= 0.125f;
            s[nt][2] *= 0.125f; s[nt][3] *= 0.125f;
            mx0 = fmaxf(mx0, fmaxf(s[nt][0], s[nt][1]));
            mx1 = fmaxf(mx1, fmaxf(s[nt][2], s[nt][3]));
        }
        mx0 = fmaxf(mx0, __shfl_xor_sync(0xffffffffu, mx0, 1));
        mx0 = fmaxf(mx0, __shfl_xor_sync(0xffffffffu, mx0, 2));
        mx1 = fmaxf(mx1, __shfl_xor_sync(0xffffffffu, mx1, 1));
        mx1 = fmaxf(mx1, __shfl_xor_sync(0xffffffffu, mx1, 2));

        float mn0 = fmaxf(m0, mx0), mn1 = fmaxf(m1, mx1);
        float c0 = __expf(m0 - mn0), c1 = __expf(m1 - mn1);
        m0 = mn0; m1 = mn1;

        // p stays fp32 in s[]; l accumulates fp32 p (exact normalization).
        float rs0 = 0.f, rs1 = 0.f;
#pragma unroll
        for (int nt = 0; nt < 8; nt++) {
            float p;
            p = __expf(s[nt][0] - mn0); s[nt][0] = p; rs0 += p;
            p = __expf(s[nt][1] - mn0); s[nt][1] = p; rs0 += p;
            p = __expf(s[nt][2] - mn1); s[nt][2] = p; rs1 += p;
            p = __expf(s[nt][3] - mn1); s[nt][3] = p; rs1 += p;
        }
        rs0 += __shfl_xor_sync(0xffffffffu, rs0, 1);
        rs0 += __shfl_xor_sync(0xffffffffu, rs0, 2);
        rs1 += __shfl_xor_sync(0xffffffffu, rs1, 1);
        rs1 += __shfl_xor_sync(0xffffffffu, rs1, 2);
        l0 = l0 * c0 + rs0;
        l1 = l1 * c1 + rs1;
#pragma unroll
        for (int nt = 0; nt < 8; nt++) {
            o[nt][0] *= c0; o[nt][1] *= c0;
            o[nt][2] *= c1; o[nt][3] *= c1;
        }

        // ---- O += P V : P split ph+pl in registers; 3 chains ----
#pragma unroll
        for (int kt = 0; kt < 4; kt++) {
            float p00 = s[2*kt][0],   p01 = s[2*kt][1],
                  p02 = s[2*kt][2],   p03 = s[2*kt][3];
            float p10 = s[2*kt+1][0], p11 = s[2*kt+1][1],
                  p12 = s[2*kt+1][2], p13 = s[2*kt+1][3];
            unsigned pah[4], pal[4];
            pah[0] = pack_bf2(p00, p01);
            pah[1] = pack_bf2(p02, p03);
            pah[2] = pack_bf2(p10, p11);
            pah[3] = pack_bf2(p12, p13);
            pal[0] = pack_bf2(p00 - bfr(p00), p01 - bfr(p01));
            pal[1] = pack_bf2(p02 - bfr(p02), p03 - bfr(p03));
            pal[2] = pack_bf2(p10 - bfr(p10), p11 - bfr(p11));
            pal[3] = pack_bf2(p12 - bfr(p12), p13 - bfr(p13));
#pragma unroll
            for (int nt = 0; nt < 8; nt++) {
                uint4 vv = *(const uint4*)(smu + 12288
                             + ((nt * 4 + kt) * 128) + lane * 4);
                mma_bf16(o[nt], pah, vv.x, vv.y);   // ph*vh
                mma_bf16(o[nt], pah, vv.z, vv.w);   // ph*vl
                mma_bf16(o[nt], pal, vv.x, vv.y);   // pl*vh
            }
        }
    }

    // ---- normalize + store [B,H,T,HD] ----
    float inv0 = 1.f / l0, inv1 = 1.f / l1;
    float* ob = ao + ((size_t)bh * NT + q0 + warp * 16) * NHD;
#pragma unroll
    for (int nt = 0; nt < 8; nt++) {
        int col = nt * 8 + 2 * g;
        *(float2*)(ob + (size_t)r * NHD + col) =
            make_float2(o[nt][0] * inv0, o[nt][1] * inv0);
        *(float2*)(ob + (size_t)(r + 8) * NHD + col) =
            make_float2(o[nt][2] * inv1, o[nt][3] * inv1);
    }
}

// ---------------------------------------------------------------------------
extern "C" void kernel_launch(void* const* d_in, const int* in_sizes, int n_in,
                              void* d_out, int out_size)
{
    const float* q  = (const float*)d_in[0];
    const float* k  = (const float*)d_in[1];
    const float* v  = (const float*)d_in[2];
    const float* Wq = (const float*)d_in[3];
    const float* bq = (const float*)d_in[4];
    const float* Wk = (const float*)d_in[5];
    const float* bk = (const float*)d_in[6];
    const float* Wv = (const float*)d_in[7];
    const float* bv = (const float*)d_in[8];
    const float* Wo = (const float*)d_in[9];
    const float* bo = (const float*)d_in[10];
    float* out = (float*)d_out;

    float *pq, *pkt, *pv, *po;
    cudaGetSymbolAddress((void**)&pq,  g_q);
    cudaGetSymbolAddress((void**)&pkt, g_kt);
    cudaGetSymbolAddress((void**)&pv,  g_v);
    cudaGetSymbolAddress((void**)&po,  g_o);

    const int gemm_smem = 65536;
    cudaFuncSetAttribute(gemm_tc<0,0>, cudaFuncAttributeMaxDynamicSharedMemorySize, gemm_smem);
    cudaFuncSetAttribute(gemm_tc<0,1>, cudaFuncAttributeMaxDynamicSharedMemorySize, gemm_smem);
    cudaFuncSetAttribute(gemm_tc<1,2>, cudaFuncAttributeMaxDynamicSharedMemorySize, gemm_smem);

    dim3 gg(ND / 128, NM / 128);   // (8, 64)

    gemm_tc<0, 0><<<gg, 256, gemm_smem>>>(q, Wq, bq, pq);
    gemm_tc<0, 1><<<gg, 256, gemm_smem>>>(k, Wk, bk, pkt);   // K proj + transpose fused
    gemm_tc<0, 0><<<gg, 256, gemm_smem>>>(v, Wv, bv, pv);

    const int attn_smem = 16384 * 4;   // 65,536 B -> 2 CTAs/SM
    cudaFuncSetAttribute(attn_mma, cudaFuncAttributeMaxDynamicSharedMemorySize, attn_smem);
    attn_mma<<<dim3(NT / 128, NB * NH), 256, attn_smem>>>(pq, pkt, pv, po);

    gemm_tc<1, 2><<<gg, 256, gemm_smem>>>(po, Wo, bo, out);
}

// round 13
// speedup vs baseline: 1.6674x; 1.6674x over previous
#include <cuda_runtime.h>
#include <cstdint>

#define NB 4
#define NT 2048
#define ND 1024
#define NH 16
#define NHD 64
#define NM (NB*NT)   // 8192 rows

// Scratch (allocation-free rule: __device__ globals).
__device__ float g_q [NB*NH*NT*NHD];   // [B,H,T,HD]
__device__ float g_kt[NB*NH*NHD*NT];   // [B,H,HD,T]  (K projected + transposed)
__device__ float g_v [NB*NH*NT*NHD];   // [B,H,T,HD]
__device__ float g_o [NB*NH*NT*NHD];   // [B,H,T,HD] attention output

__device__ __forceinline__ unsigned f2tf(float f) {
    unsigned u;
    asm("cvt.rna.tf32.f32 %0, %1;" : "=r"(u) : "f"(f));
    return u;
}
__device__ __forceinline__ float tf32r(float f) { return __uint_as_float(f2tf(f)); }

__device__ __forceinline__ void mma_tf32(float c[4], const unsigned a[4], const unsigned b[2]) {
    asm volatile(
        "mma.sync.aligned.m16n8k8.row.col.f32.tf32.tf32.f32 "
        "{%0,%1,%2,%3}, {%4,%5,%6,%7}, {%8,%9}, {%0,%1,%2,%3};"
        : "+f"(c[0]), "+f"(c[1]), "+f"(c[2]), "+f"(c[3])
        : "r"(a[0]), "r"(a[1]), "r"(a[2]), "r"(a[3]), "r"(b[0]), "r"(b[1]));
}
__device__ __forceinline__ void mma_f(float c[4], const float a[4], const float b0, const float b1) {
    asm volatile(
        "mma.sync.aligned.m16n8k8.row.col.f32.tf32.tf32.f32 "
        "{%0,%1,%2,%3}, {%4,%5,%6,%7}, {%8,%9}, {%0,%1,%2,%3};"
        : "+f"(c[0]), "+f"(c[1]), "+f"(c[2]), "+f"(c[3])
        : "r"(__float_as_uint(a[0])), "r"(__float_as_uint(a[1])),
          "r"(__float_as_uint(a[2])), "r"(__float_as_uint(a[3])),
          "r"(__float_as_uint(b0)),   "r"(__float_as_uint(b1)));
}

// ---------------------------------------------------------------------------
// Tensor-core tf32 GEMM (verbatim from passing R3/R5-R8): C = A@W^T + bias.
// ---------------------------------------------------------------------------
template<int AMODE, int OMODE>
__global__ __launch_bounds__(256)
void gemm_tc(const float* __restrict__ A, const float* __restrict__ W,
             const float* __restrict__ bias, float* __restrict__ Cout)
{
    extern __shared__ unsigned sh[];
    unsigned* As = sh;           // 2 bufs x 4096 u32
    unsigned* Ws = sh + 8192;

    const int tid  = threadIdx.x;
    const int lane = tid & 31;
    const int warp = tid >> 5;
    const int wm   = warp & 1;
    const int wn   = warp >> 1;
    const int bm   = blockIdx.y * 128;
    const int bn   = blockIdx.x * 128;

    float acc[4][4][4];
#pragma unroll
    for (int mi = 0; mi < 4; mi++)
#pragma unroll
        for (int nj = 0; nj < 4; nj++)
#pragma unroll
            for (int r = 0; r < 4; r++) acc[mi][nj][r] = 0.f;

    float4 ar[4], wr[4];

    auto ldg = [&](int s) {
#pragma unroll
        for (int l = 0; l < 4; l++) {
            int idx = l * 256 + tid;
            int row = idx >> 3;
            int kq  = idx & 7;
            int kg  = s * 32 + kq * 4;
            if (AMODE == 0) {
                ar[l] = *(const float4*)(A + (size_t)(bm + row) * ND + kg);
            } else {
                int m  = bm + row;
                int b_ = m >> 11, t_ = m & (NT - 1);
                int h_ = kg >> 6, hd = kg & 63;
                ar[l] = *(const float4*)(A + (((size_t)(b_ * NH + h_) * NT + t_) * NHD + hd));
            }
            wr[l] = *(const float4*)(W + (size_t)(bn + row) * ND + kg);
        }
    };

    auto sts = [&](int buf) {
        unsigned* ab = As + buf * 4096;
        unsigned* wb = Ws + buf * 4096;
#pragma unroll
        for (int l = 0; l < 4; l++) {
            int idx = l * 256 + tid;
            int row = idx >> 3;
            int kq  = idx & 7;
            {
                unsigned* p = ab + (((row >> 4) * 4 + (kq >> 1)) << 7);
                int reg = ((kq & 1) << 1) + ((row >> 3) & 1);
                int lb  = (row & 7) * 4;
                p[(lb + 0) * 4 + reg] = f2tf(ar[l].x);
                p[(lb + 1) * 4 + reg] = f2tf(ar[l].y);
                p[(lb + 2) * 4 + reg] = f2tf(ar[l].z);
                p[(lb + 3) * 4 + reg] = f2tf(ar[l].w);
            }
            {
                unsigned* p = wb + (((row >> 3) * 4 + (kq >> 1)) << 6);
                int reg = (kq & 1);
                int lb  = (row & 7) * 4;
                p[(lb + 0) * 2 + reg] = f2tf(wr[l].x);
                p[(lb + 1) * 2 + reg] = f2tf(wr[l].y);
                p[(lb + 2) * 2 + reg] = f2tf(wr[l].z);
                p[(lb + 3) * 2 + reg] = f2tf(wr[l].w);
            }
        }
    };

    auto compute = [&](int buf) {
        const unsigned* ab = As + buf * 4096;
        const unsigned* wb = Ws + buf * 4096;
#pragma unroll
        for (int kt = 0; kt < 4; kt++) {
            unsigned af[4][4];
#pragma unroll
            for (int mi = 0; mi < 4; mi++) {
                uint4 t = *(const uint4*)(ab + ((((wm * 4 + mi) * 4 + kt)) << 7) + (lane << 2));
                af[mi][0] = t.x; af[mi][1] = t.y; af[mi][2] = t.z; af[mi][3] = t.w;
            }
            unsigned bf[4][2];
#pragma unroll
            for (int nj = 0; nj < 4; nj++) {
                uint2 t = *(const uint2*)(wb + ((((wn * 4 + nj) * 4 + kt)) << 6) + (lane << 1));
                bf[nj][0] = t.x; bf[nj][1] = t.y;
            }
#pragma unroll
            for (int mi = 0; mi < 4; mi++)
#pragma unroll
                for (int nj = 0; nj < 4; nj++)
                    mma_tf32(acc[mi][nj], af[mi], bf[nj]);
        }
    };

    ldg(0);
    sts(0);
    __syncthreads();
    for (int s = 0; s < 32; s++) {
        int buf = s & 1;
        if (s < 31) ldg(s + 1);
        compute(buf);
        if (s < 31) sts(buf ^ 1);
        __syncthreads();
    }

#pragma unroll
    for (int nj = 0; nj < 4; nj++) {
        int col = bn + (wn * 4 + nj) * 8 + (lane & 3) * 2;
        float b0 = bias[col], b1 = bias[col + 1];
#pragma unroll
        for (int mi = 0; mi < 4; mi++) {
            int row = bm + (wm * 4 + mi) * 16 + (lane >> 2);
            float v00 = acc[mi][nj][0] + b0, v01 = acc[mi][nj][1] + b1;
            float v10 = acc[mi][nj][2] + b0, v11 = acc[mi][nj][3] + b1;
            if (OMODE == 2) {
                *(float2*)(Cout + (size_t)row * ND + col)       = make_float2(v00, v01);
                *(float2*)(Cout + (size_t)(row + 8) * ND + col) = make_float2(v10, v11);
            } else if (OMODE == 0) {
                int b_ = row >> 11, t_ = row & (NT - 1);
                int h_ = col >> 6, hd = col & 63;
                float* p = Cout + (((size_t)(b_ * NH + h_) * NT + t_) * NHD + hd);
                *(float2*)p             = make_float2(v00, v01);
                *(float2*)(p + 8 * NHD) = make_float2(v10, v11);
            } else { // OMODE 1: [B,H,HD,T]
                int b_ = row >> 11, t_ = row & (NT - 1);
                int h_ = col >> 6, hd = col & 63;
                float* p = Cout + (((size_t)(b_ * NH + h_) * NHD + hd) * NT + t_);
                p[0]      = v00;
                p[NT]     = v01;
                p[8]      = v10;
                p[NT + 8] = v11;
            }
        }
    }
}

// ---------------------------------------------------------------------------
// Flash attention v8: R8 (fragment-order staging, 8 warps, 128-q tile) with
// compact K (hi only) and 2-chain S = qh*kh + ql*kh.
// Dropped term qh*kl adds ~2e-4 to O; total budget ~6.8e-4 < 1e-3.
// smem (u32), 96 KB -> 2 CTAs/SM:
//  QH [0,8192)      tile(mt*8+kt)*128: uint4/lane = A-frag
//  QL [8192,16384)
//  KH [16384,20480) tile(nt*8+kt)*64 : uint2/lane = (b0,b1) hi only
//  VH [20480,24576) tile(nt*8+kt)*64 : uint2/lane
// ---------------------------------------------------------------------------
__global__ __launch_bounds__(256, 2)
void attn_mma(const float* __restrict__ qp, const float* __restrict__ ktp,
              const float* __restrict__ vp, float* __restrict__ ao)
{
    extern __shared__ unsigned smu[];

    const int tid  = threadIdx.x;
    const int lane = tid & 31;
    const int warp = tid >> 5;
    const int r    = lane >> 2;          // 0..7
    const int g    = lane & 3;           // 0..3
    const int bh   = blockIdx.y;
    const int q0   = blockIdx.x * 128;

    const float* qb = qp  + ((size_t)bh * NT + q0) * NHD;
    const float* kb = ktp + (size_t)bh * NHD * NT;
    const float* vb = vp  + (size_t)bh * NT * NHD;

    // ---- Stage Q once in A-frag order (hi/lo). 2048 float4, 8 iters. ----
#pragma unroll
    for (int i = 0; i < 8; i++) {
        int idx = i * 256 + tid;
        int uu = idx & 31, blk = idx >> 5;          // warp spans 8 rows x 4 f4
        int qrow = (uu >> 2) + (blk & 15) * 8;      // 0..127
        int f4   = (uu & 3) + (blk >> 4) * 4;       // 0..15
        float4 x = *(const float4*)(qb + qrow * NHD + f4 * 4);
        float xe[4] = {x.x, x.y, x.z, x.w};
        int mt = qrow >> 4;
        int lb = (qrow & 7) * 4;
        int rr = (qrow >> 3) & 1;
#pragma unroll
        for (int e = 0; e < 4; e++) {
            int hd = f4 * 4 + e;
            int ad = ((mt * 8 + (hd >> 3)) * 128) + (lb + (hd & 3)) * 4
                     + ((hd >> 2) & 1) * 2 + rr;
            float h = tf32r(xe[e]);
            smu[ad]        = __float_as_uint(h);
            smu[8192 + ad] = f2tf(xe[e] - h);
        }
    }

    float o[8][4];
#pragma unroll
    for (int nt = 0; nt < 8; nt++)
#pragma unroll
        for (int c = 0; c < 4; c++) o[nt][c] = 0.f;
    float m0 = -1e30f, m1 = -1e30f, l0 = 0.f, l1 = 0.f;

    for (int t0 = 0; t0 < NT; t0 += 64) {
        __syncthreads();   // prev compute done before restaging (covers Q on iter 0)
        // ---- Stage K (hi only) and V in B-frag order. ----
#pragma unroll
        for (int i = 0; i < 4; i++) {
            int idx = i * 256 + tid;
            int uu = idx & 31, blk = idx >> 5;      // 0..31
            int row = (uu >> 2) + (blk & 7) * 8;    // 0..63
            int f4  = (uu & 3) + (blk >> 3) * 4;    // 0..15
            {   // K: row = hd, f4 indexes keys; hi only
                float4 x = *(const float4*)(kb + (size_t)row * NT + t0 + f4 * 4);
                float xe[4] = {x.x, x.y, x.z, x.w};
                int kt = row >> 3;
                int reg = (row >> 2) & 1;
                int lh = row & 3;
#pragma unroll
                for (int e = 0; e < 4; e++) {
                    int key = f4 * 4 + e;
                    int ad = 16384 + (((key >> 3) * 8 + kt) * 64)
                             + ((key & 7) * 4 + lh) * 2 + reg;
                    smu[ad] = f2tf(xe[e]);
                }
            }
            {   // V: row = key, f4 indexes hd
                float4 y = *(const float4*)(vb + (size_t)(t0 + row) * NHD + f4 * 4);
                float ye[4] = {y.x, y.y, y.z, y.w};
                int kt = row >> 3;
                int reg = (row >> 2) & 1;
                int lk = row & 3;
#pragma unroll
                for (int e = 0; e < 4; e++) {
                    int hd = f4 * 4 + e;
                    int ad = 20480 + (((hd >> 3) * 8 + kt) * 64)
                             + ((hd & 7) * 4 + lk) * 2 + reg;
                    smu[ad] = f2tf(ye[e]);
                }
            }
        }
        __syncthreads();

        // ---- S = Q K^T : 2 chains (qh*kh + ql*kh), Kh LDS.64 frags ----
        float s[8][4];
#pragma unroll
        for (int nt = 0; nt < 8; nt++)
#pragma unroll
            for (int c = 0; c < 4; c++) s[nt][c] = 0.f;

#pragma unroll
        for (int kt = 0; kt < 8; kt++) {
            uint4 qh4 = *(const uint4*)(smu + (warp * 8 + kt) * 128 + lane * 4);
            uint4 ql4 = *(const uint4*)(smu + 8192 + (warp * 8 + kt) * 128 + lane * 4);
            float ah[4] = {__uint_as_float(qh4.x), __uint_as_float(qh4.y),
                           __uint_as_float(qh4.z), __uint_as_float(qh4.w)};
            float al[4] = {__uint_as_float(ql4.x), __uint_as_float(ql4.y),
                           __uint_as_float(ql4.z), __uint_as_float(ql4.w)};
#pragma unroll
            for (int half = 0; half < 2; half++) {
                uint2 kk[4];
#pragma unroll
                for (int j = 0; j < 4; j++)
                    kk[j] = *(const uint2*)(smu + 16384
                              + (((half * 4 + j) * 8 + kt) * 64) + lane * 2);
#pragma unroll
                for (int j = 0; j < 4; j++)
                    mma_f(s[half*4+j], ah, __uint_as_float(kk[j].x), __uint_as_float(kk[j].y));
#pragma unroll
                for (int j = 0; j < 4; j++)
                    mma_f(s[half*4+j], al, __uint_as_float(kk[j].x), __uint_as_float(kk[j].y));
            }
        }

        // ---- online softmax (rows r, r+8; quad-wide reductions) ----
        float mx0 = -1e30f, mx1 = -1e30f;
#pragma unroll
        for (int nt = 0; nt < 8; nt++) {
            s[nt][0] *= 0.125f; s[nt][1] *= 0.125f;
            s[nt][2] *= 0.125f; s[nt][3] *= 0.125f;
            mx0 = fmaxf(mx0, fmaxf(s[nt][0], s[nt][1]));
            mx1 = fmaxf(mx1, fmaxf(s[nt][2], s[nt][3]));
        }
        mx0 = fmaxf(mx0, __shfl_xor_sync(0xffffffffu, mx0, 1));
        mx0 = fmaxf(mx0, __shfl_xor_sync(0xffffffffu, mx0, 2));
        mx1 = fmaxf(mx1, __shfl_xor_sync(0xffffffffu, mx1, 1));
        mx1 = fmaxf(mx1, __shfl_xor_sync(0xffffffffu, mx1, 2));

        float mn0 = fmaxf(m0, mx0), mn1 = fmaxf(m1, mx1);
        float c0 = __expf(m0 - mn0), c1 = __expf(m1 - mn1);
        m0 = mn0; m1 = mn1;

        float rs0 = 0.f, rs1 = 0.f;
#pragma unroll
        for (int nt = 0; nt < 8; nt++) {
            float p;
            p = tf32r(__expf(s[nt][0] - mn0)); s[nt][0] = p; rs0 += p;
            p = tf32r(__expf(s[nt][1] - mn0)); s[nt][1] = p; rs0 += p;
            p = tf32r(__expf(s[nt][2] - mn1)); s[nt][2] = p; rs1 += p;
            p = tf32r(__expf(s[nt][3] - mn1)); s[nt][3] = p; rs1 += p;
        }
        rs0 += __shfl_xor_sync(0xffffffffu, rs0, 1);
        rs0 += __shfl_xor_sync(0xffffffffu, rs0, 2);
        rs1 += __shfl_xor_sync(0xffffffffu, rs1, 1);
        rs1 += __shfl_xor_sync(0xffffffffu, rs1, 2);
        l0 = l0 * c0 + rs0;
        l1 = l1 * c1 + rs1;
#pragma unroll
        for (int nt = 0; nt < 8; nt++) {
            o[nt][0] *= c0; o[nt][1] *= c0;
            o[nt][2] *= c1; o[nt][3] *= c1;
        }

        // ---- O += P V : P C-frag -> A-frag via quad shuffles; LDS.64 V frags ----
        const int src1 = (lane & ~3) | (g >> 1);
        const int src2 = src1 + 2;
        const bool odd = (g & 1) != 0;
#pragma unroll
        for (int kt = 0; kt < 8; kt++) {
            float x0 = __shfl_sync(0xffffffffu, s[kt][0], src1);
            float x1 = __shfl_sync(0xffffffffu, s[kt][1], src1);
            float y0 = __shfl_sync(0xffffffffu, s[kt][2], src1);
            float y1 = __shfl_sync(0xffffffffu, s[kt][3], src1);
            float z0 = __shfl_sync(0xffffffffu, s[kt][0], src2);
            float z1 = __shfl_sync(0xffffffffu, s[kt][1], src2);
            float w0 = __shfl_sync(0xffffffffu, s[kt][2], src2);
            float w1 = __shfl_sync(0xffffffffu, s[kt][3], src2);
            float a[4];
            a[0] = odd ? x1 : x0;
            a[1] = odd ? y1 : y0;
            a[2] = odd ? z1 : z0;
            a[3] = odd ? w1 : w0;

#pragma unroll
            for (int nt = 0; nt < 8; nt++) {
                uint2 vv = *(const uint2*)(smu + 20480 + ((nt * 8 + kt) * 64) + lane * 2);
                mma_f(o[nt], a, __uint_as_float(vv.x), __uint_as_float(vv.y));
            }
        }
    }

    // ---- normalize + store [B,H,T,HD] ----
    float inv0 = 1.f / l0, inv1 = 1.f / l1;
    float* ob = ao + ((size_t)bh * NT + q0 + warp * 16) * NHD;
#pragma unroll
    for (int nt = 0; nt < 8; nt++) {
        int col = nt * 8 + 2 * g;
        *(float2*)(ob + (size_t)r * NHD + col) =
            make_float2(o[nt][0] * inv0, o[nt][1] * inv0);
        *(float2*)(ob + (size_t)(r + 8) * NHD + col) =
            make_float2(o[nt][2] * inv1, o[nt][3] * inv1);
    }
}

// ---------------------------------------------------------------------------
extern "C" void kernel_launch(void* const* d_in, const int* in_sizes, int n_in,
                              void* d_out, int out_size)
{
    const float* q  = (const float*)d_in[0];
    const float* k  = (const float*)d_in[1];
    const float* v  = (const float*)d_in[2];
    const float* Wq = (const float*)d_in[3];
    const float* bq = (const float*)d_in[4];
    const float* Wk = (const float*)d_in[5];
    const float* bk = (const float*)d_in[6];
    const float* Wv = (const float*)d_in[7];
    const float* bv = (const float*)d_in[8];
    const float* Wo = (const float*)d_in[9];
    const float* bo = (const float*)d_in[10];
    float* out = (float*)d_out;

    float *pq, *pkt, *pv, *po;
    cudaGetSymbolAddress((void**)&pq,  g_q);
    cudaGetSymbolAddress((void**)&pkt, g_kt);
    cudaGetSymbolAddress((void**)&pv,  g_v);
    cudaGetSymbolAddress((void**)&po,  g_o);

    const int gemm_smem = 65536;
    cudaFuncSetAttribute(gemm_tc<0,0>, cudaFuncAttributeMaxDynamicSharedMemorySize, gemm_smem);
    cudaFuncSetAttribute(gemm_tc<0,1>, cudaFuncAttributeMaxDynamicSharedMemorySize, gemm_smem);
    cudaFuncSetAttribute(gemm_tc<1,2>, cudaFuncAttributeMaxDynamicSharedMemorySize, gemm_smem);

    dim3 gg(ND / 128, NM / 128);   // (8, 64)

    gemm_tc<0, 0><<<gg, 256, gemm_smem>>>(q, Wq, bq, pq);
    gemm_tc<0, 1><<<gg, 256, gemm_smem>>>(k, Wk, bk, pkt);   // K proj + transpose fused
    gemm_tc<0, 0><<<gg, 256, gemm_smem>>>(v, Wv, bv, pv);

    const int attn_smem = 24576 * 4;   // 98,304 B -> 2 CTAs/SM
    cudaFuncSetAttribute(attn_mma, cudaFuncAttributeMaxDynamicSharedMemorySize, attn_smem);
    attn_mma<<<dim3(NT / 128, NB * NH), 256, attn_smem>>>(pq, pkt, pv, po);

    gemm_tc<1, 2><<<gg, 256, gemm_smem>>>(po, Wo, bo, out);
}

// round 14
// speedup vs baseline: 1.7927x; 1.0751x over previous
#include <cuda_runtime.h>
#include <cstdint>

#define NB 4
#define NT 2048
#define ND 1024
#define NH 16
#define NHD 64
#define NM (NB*NT)   // 8192 rows

// Scratch (allocation-free rule: __device__ globals).
__device__ float g_q [NB*NH*NT*NHD];   // [B,H,T,HD]
__device__ float g_kt[NB*NH*NHD*NT];   // [B,H,HD,T]  (K projected + transposed)
__device__ float g_v [NB*NH*NT*NHD];   // [B,H,T,HD]
__device__ float g_o [NB*NH*NT*NHD];   // [B,H,T,HD] attention output

__device__ __forceinline__ unsigned f2tf(float f) {
    unsigned u;
    asm("cvt.rna.tf32.f32 %0, %1;" : "=r"(u) : "f"(f));
    return u;
}
__device__ __forceinline__ float tf32r(float f) { return __uint_as_float(f2tf(f)); }

__device__ __forceinline__ void mma_tf32(float c[4], const unsigned a[4], const unsigned b[2]) {
    asm volatile(
        "mma.sync.aligned.m16n8k8.row.col.f32.tf32.tf32.f32 "
        "{%0,%1,%2,%3}, {%4,%5,%6,%7}, {%8,%9}, {%0,%1,%2,%3};"
        : "+f"(c[0]), "+f"(c[1]), "+f"(c[2]), "+f"(c[3])
        : "r"(a[0]), "r"(a[1]), "r"(a[2]), "r"(a[3]), "r"(b[0]), "r"(b[1]));
}
__device__ __forceinline__ void mma_f(float c[4], const float a[4], const float b0, const float b1) {
    asm volatile(
        "mma.sync.aligned.m16n8k8.row.col.f32.tf32.tf32.f32 "
        "{%0,%1,%2,%3}, {%4,%5,%6,%7}, {%8,%9}, {%0,%1,%2,%3};"
        : "+f"(c[0]), "+f"(c[1]), "+f"(c[2]), "+f"(c[3])
        : "r"(__float_as_uint(a[0])), "r"(__float_as_uint(a[1])),
          "r"(__float_as_uint(a[2])), "r"(__float_as_uint(a[3])),
          "r"(__float_as_uint(b0)),   "r"(__float_as_uint(b1)));
}

// ---------------------------------------------------------------------------
// GEMM core (same tiling as the passing R3/R5-R13 kernel). Runtime epilogue.
// ---------------------------------------------------------------------------
struct GemmCore {
    unsigned* As;
    unsigned* Ws;
    int tid, lane, warp, wm, wn, bm, bn;
    float acc[4][4][4];
    float4 ar[4], wr[4];

    __device__ __forceinline__ void init(unsigned* sh, int bm_, int bn_) {
        As = sh; Ws = sh + 8192;
        tid = threadIdx.x; lane = tid & 31; warp = tid >> 5;
        wm = warp & 1; wn = warp >> 1;
        bm = bm_; bn = bn_;
#pragma unroll
        for (int mi = 0; mi < 4; mi++)
#pragma unroll
            for (int nj = 0; nj < 4; nj++)
#pragma unroll
                for (int r = 0; r < 4; r++) acc[mi][nj][r] = 0.f;
    }

    template<int AMODE>
    __device__ __forceinline__ void ldg(const float* __restrict__ A,
                                        const float* __restrict__ W, int s) {
#pragma unroll
        for (int l = 0; l < 4; l++) {
            int idx = l * 256 + tid;
            int row = idx >> 3;
            int kq  = idx & 7;
            int kg  = s * 32 + kq * 4;
            if (AMODE == 0) {
                ar[l] = *(const float4*)(A + (size_t)(bm + row) * ND + kg);
            } else {
                int m  = bm + row;
                int b_ = m >> 11, t_ = m & (NT - 1);
                int h_ = kg >> 6, hd = kg & 63;
                ar[l] = *(const float4*)(A + (((size_t)(b_ * NH + h_) * NT + t_) * NHD + hd));
            }
            wr[l] = *(const float4*)(W + (size_t)(bn + row) * ND + kg);
        }
    }

    __device__ __forceinline__ void sts(int buf) {
        unsigned* ab = As + buf * 4096;
        unsigned* wb = Ws + buf * 4096;
#pragma unroll
        for (int l = 0; l < 4; l++) {
            int idx = l * 256 + tid;
            int row = idx >> 3;
            int kq  = idx & 7;
            {
                unsigned* p = ab + (((row >> 4) * 4 + (kq >> 1)) << 7);
                int reg = ((kq & 1) << 1) + ((row >> 3) & 1);
                int lb  = (row & 7) * 4;
                p[(lb + 0) * 4 + reg] = f2tf(ar[l].x);
                p[(lb + 1) * 4 + reg] = f2tf(ar[l].y);
                p[(lb + 2) * 4 + reg] = f2tf(ar[l].z);
                p[(lb + 3) * 4 + reg] = f2tf(ar[l].w);
            }
            {
                unsigned* p = wb + (((row >> 3) * 4 + (kq >> 1)) << 6);
                int reg = (kq & 1);
                int lb  = (row & 7) * 4;
                p[(lb + 0) * 2 + reg] = f2tf(wr[l].x);
                p[(lb + 1) * 2 + reg] = f2tf(wr[l].y);
                p[(lb + 2) * 2 + reg] = f2tf(wr[l].z);
                p[(lb + 3) * 2 + reg] = f2tf(wr[l].w);
            }
        }
    }

    __device__ __forceinline__ void compute(int buf) {
        const unsigned* ab = As + buf * 4096;
        const unsigned* wb = Ws + buf * 4096;
#pragma unroll
        for (int kt = 0; kt < 4; kt++) {
            unsigned af[4][4];
#pragma unroll
            for (int mi = 0; mi < 4; mi++) {
                uint4 t = *(const uint4*)(ab + ((((wm * 4 + mi) * 4 + kt)) << 7) + (lane << 2));
                af[mi][0] = t.x; af[mi][1] = t.y; af[mi][2] = t.z; af[mi][3] = t.w;
            }
            unsigned bf[4][2];
#pragma unroll
            for (int nj = 0; nj < 4; nj++) {
                uint2 t = *(const uint2*)(wb + ((((wn * 4 + nj) * 4 + kt)) << 6) + (lane << 1));
                bf[nj][0] = t.x; bf[nj][1] = t.y;
            }
#pragma unroll
            for (int mi = 0; mi < 4; mi++)
#pragma unroll
                for (int nj = 0; nj < 4; nj++)
                    mma_tf32(acc[mi][nj], af[mi], bf[nj]);
        }
    }

    // omode: 0 -> [B,H,T,HD]; 1 -> [B,H,HD,T]; 2 -> row-major [M,N]
    __device__ __forceinline__ void epilogue(const float* __restrict__ bias,
                                             float* __restrict__ Cout, int omode) {
#pragma unroll
        for (int nj = 0; nj < 4; nj++) {
            int col = bn + (wn * 4 + nj) * 8 + (lane & 3) * 2;
            float b0 = bias[col], b1 = bias[col + 1];
#pragma unroll
            for (int mi = 0; mi < 4; mi++) {
                int row = bm + (wm * 4 + mi) * 16 + (lane >> 2);
                float v00 = acc[mi][nj][0] + b0, v01 = acc[mi][nj][1] + b1;
                float v10 = acc[mi][nj][2] + b0, v11 = acc[mi][nj][3] + b1;
                if (omode == 2) {
                    *(float2*)(Cout + (size_t)row * ND + col)       = make_float2(v00, v01);
                    *(float2*)(Cout + (size_t)(row + 8) * ND + col) = make_float2(v10, v11);
                } else if (omode == 0) {
                    int b_ = row >> 11, t_ = row & (NT - 1);
                    int h_ = col >> 6, hd = col & 63;
                    float* p = Cout + (((size_t)(b_ * NH + h_) * NT + t_) * NHD + hd);
                    *(float2*)p             = make_float2(v00, v01);
                    *(float2*)(p + 8 * NHD) = make_float2(v10, v11);
                } else { // omode 1: [B,H,HD,T]
                    int b_ = row >> 11, t_ = row & (NT - 1);
                    int h_ = col >> 6, hd = col & 63;
                    float* p = Cout + (((size_t)(b_ * NH + h_) * NHD + hd) * NT + t_);
                    p[0]      = v00;
                    p[NT]     = v01;
                    p[8]      = v10;
                    p[NT + 8] = v11;
                }
            }
        }
    }
};

// Fused Q/K/V projection: grid (24, 64); blockIdx.x = which*8 + bn_idx.
// which 0 -> A=qin, W=Wq, out=oq (omode 0)
// which 1 -> A=kin, W=Wk, out=okt (omode 1, fused transpose)
// which 2 -> A=vin, W=Wv, out=ov (omode 0)
__global__ __launch_bounds__(256)
void gemm_qkv(const float* __restrict__ qin, const float* __restrict__ kin,
              const float* __restrict__ vin,
              const float* __restrict__ Wq, const float* __restrict__ bq,
              const float* __restrict__ Wk, const float* __restrict__ bk,
              const float* __restrict__ Wv, const float* __restrict__ bv,
              float* __restrict__ oq, float* __restrict__ okt, float* __restrict__ ov)
{
    extern __shared__ unsigned sh[];
    const int which = blockIdx.x >> 3;
    const int bn = (blockIdx.x & 7) * 128;
    const int bm = blockIdx.y * 128;
    const float* A    = (which == 0) ? qin : (which == 1) ? kin : vin;
    const float* W    = (which == 0) ? Wq  : (which == 1) ? Wk  : Wv;
    const float* bias = (which == 0) ? bq  : (which == 1) ? bk  : bv;
    float* Cout       = (which == 0) ? oq  : (which == 1) ? okt : ov;
    const int omode   = (which == 1) ? 1 : 0;

    GemmCore gc;
    gc.init(sh, bm, bn);
    gc.ldg<0>(A, W, 0);
    gc.sts(0);
    __syncthreads();
    for (int s = 0; s < 32; s++) {
        int buf = s & 1;
        if (s < 31) gc.ldg<0>(A, W, s + 1);
        gc.compute(buf);
        if (s < 31) gc.sts(buf ^ 1);
        __syncthreads();
    }
    gc.epilogue(bias, Cout, omode);
}

// Output projection: A gathered from head layout, row-major out.
__global__ __launch_bounds__(256)
void gemm_out(const float* __restrict__ A, const float* __restrict__ W,
              const float* __restrict__ bias, float* __restrict__ Cout)
{
    extern __shared__ unsigned sh[];
    GemmCore gc;
    gc.init(sh, blockIdx.y * 128, blockIdx.x * 128);
    gc.ldg<1>(A, W, 0);
    gc.sts(0);
    __syncthreads();
    for (int s = 0; s < 32; s++) {
        int buf = s & 1;
        if (s < 31) gc.ldg<1>(A, W, s + 1);
        gc.compute(buf);
        if (s < 31) gc.sts(buf ^ 1);
        __syncthreads();
    }
    gc.epilogue(bias, Cout, 2);
}

// ---------------------------------------------------------------------------
// Flash attention v9: R13 minus the ql*kh chain (single-chain pure-tf32 S).
// 256 threads = 8 warps; CTA = 128 queries; warp owns 16 rows (mt = warp).
// smem (u32), 64 KB -> 2 CTAs/SM:
//  QH [0,8192)      tile(mt*8+kt)*128: uint4/lane = A-frag
//  KH [8192,12288)  tile(nt*8+kt)*64 : uint2/lane
//  VH [12288,16384) tile(nt*8+kt)*64 : uint2/lane
// ---------------------------------------------------------------------------
__global__ __launch_bounds__(256, 2)
void attn_mma(const float* __restrict__ qp, const float* __restrict__ ktp,
              const float* __restrict__ vp, float* __restrict__ ao)
{
    extern __shared__ unsigned smu[];

    const int tid  = threadIdx.x;
    const int lane = tid & 31;
    const int warp = tid >> 5;
    const int r    = lane >> 2;          // 0..7
    const int g    = lane & 3;           // 0..3
    const int bh   = blockIdx.y;
    const int q0   = blockIdx.x * 128;

    const float* qb = qp  + ((size_t)bh * NT + q0) * NHD;
    const float* kb = ktp + (size_t)bh * NHD * NT;
    const float* vb = vp  + (size_t)bh * NT * NHD;

    // ---- Stage Q once in A-frag order (hi only). 2048 float4, 8 iters. ----
#pragma unroll
    for (int i = 0; i < 8; i++) {
        int idx = i * 256 + tid;
        int uu = idx & 31, blk = idx >> 5;          // warp spans 8 rows x 4 f4
        int qrow = (uu >> 2) + (blk & 15) * 8;      // 0..127
        int f4   = (uu & 3) + (blk >> 4) * 4;       // 0..15
        float4 x = *(const float4*)(qb + qrow * NHD + f4 * 4);
        float xe[4] = {x.x, x.y, x.z, x.w};
        int mt = qrow >> 4;
        int lb = (qrow & 7) * 4;
        int rr = (qrow >> 3) & 1;
#pragma unroll
        for (int e = 0; e < 4; e++) {
            int hd = f4 * 4 + e;
            int ad = ((mt * 8 + (hd >> 3)) * 128) + (lb + (hd & 3)) * 4
                     + ((hd >> 2) & 1) * 2 + rr;
            smu[ad] = f2tf(xe[e]);
        }
    }

    float o[8][4];
#pragma unroll
    for (int nt = 0; nt < 8; nt++)
#pragma unroll
        for (int c = 0; c < 4; c++) o[nt][c] = 0.f;
    float m0 = -1e30f, m1 = -1e30f, l0 = 0.f, l1 = 0.f;

    for (int t0 = 0; t0 < NT; t0 += 64) {
        __syncthreads();   // prev compute done before restaging (covers Q on iter 0)
        // ---- Stage K and V (hi only) in B-frag order. ----
#pragma unroll
        for (int i = 0; i < 4; i++) {
            int idx = i * 256 + tid;
            int uu = idx & 31, blk = idx >> 5;      // 0..31
            int row = (uu >> 2) + (blk & 7) * 8;    // 0..63
            int f4  = (uu & 3) + (blk >> 3) * 4;    // 0..15
            {   // K: row = hd, f4 indexes keys
                float4 x = *(const float4*)(kb + (size_t)row * NT + t0 + f4 * 4);
                float xe[4] = {x.x, x.y, x.z, x.w};
                int kt = row >> 3;
                int reg = (row >> 2) & 1;
                int lh = row & 3;
#pragma unroll
                for (int e = 0; e < 4; e++) {
                    int key = f4 * 4 + e;
                    int ad = 8192 + (((key >> 3) * 8 + kt) * 64)
                             + ((key & 7) * 4 + lh) * 2 + reg;
                    smu[ad] = f2tf(xe[e]);
                }
            }
            {   // V: row = key, f4 indexes hd
                float4 y = *(const float4*)(vb + (size_t)(t0 + row) * NHD + f4 * 4);
                float ye[4] = {y.x, y.y, y.z, y.w};
                int kt = row >> 3;
                int reg = (row >> 2) & 1;
                int lk = row & 3;
#pragma unroll
                for (int e = 0; e < 4; e++) {
                    int hd = f4 * 4 + e;
                    int ad = 12288 + (((hd >> 3) * 8 + kt) * 64)
                             + ((hd & 7) * 4 + lk) * 2 + reg;
                    smu[ad] = f2tf(ye[e]);
                }
            }
        }
        __syncthreads();

        // ---- S = Q K^T : single chain (pure tf32) ----
        float s[8][4];
#pragma unroll
        for (int nt = 0; nt < 8; nt++)
#pragma unroll
            for (int c = 0; c < 4; c++) s[nt][c] = 0.f;

#pragma unroll
        for (int kt = 0; kt < 8; kt++) {
            uint4 qh4 = *(const uint4*)(smu + (warp * 8 + kt) * 128 + lane * 4);
            float ah[4] = {__uint_as_float(qh4.x), __uint_as_float(qh4.y),
                           __uint_as_float(qh4.z), __uint_as_float(qh4.w)};
#pragma unroll
            for (int half = 0; half < 2; half++) {
                uint2 kk[4];
#pragma unroll
                for (int j = 0; j < 4; j++)
                    kk[j] = *(const uint2*)(smu + 8192
                              + (((half * 4 + j) * 8 + kt) * 64) + lane * 2);
#pragma unroll
                for (int j = 0; j < 4; j++)
                    mma_f(s[half*4+j], ah, __uint_as_float(kk[j].x), __uint_as_float(kk[j].y));
            }
        }

        // ---- online softmax (rows r, r+8; quad-wide reductions) ----
        float mx0 = -1e30f, mx1 = -1e30f;
#pragma unroll
        for (int nt = 0; nt < 8; nt++) {
            s[nt][0] *= 0.125f; s[nt][1] *= 0.125f;
            s[nt][2] *= 0.125f; s[nt][3] *= 0.125f;
            mx0 = fmaxf(mx0, fmaxf(s[nt][0], s[nt][1]));
            mx1 = fmaxf(mx1, fmaxf(s[nt][2], s[nt][3]));
        }
        mx0 = fmaxf(mx0, __shfl_xor_sync(0xffffffffu, mx0, 1));
        mx0 = fmaxf(mx0, __shfl_xor_sync(0xffffffffu, mx0, 2));
        mx1 = fmaxf(mx1, __shfl_xor_sync(0xffffffffu, mx1, 1));
        mx1 = fmaxf(mx1, __shfl_xor_sync(0xffffffffu, mx1, 2));

        float mn0 = fmaxf(m0, mx0), mn1 = fmaxf(m1, mx1);
        float c0 = __expf(m0 - mn0), c1 = __expf(m1 - mn1);
        m0 = mn0; m1 = mn1;

        float rs0 = 0.f, rs1 = 0.f;
#pragma unroll
        for (int nt = 0; nt < 8; nt++) {
            float p;
            p = tf32r(__expf(s[nt][0] - mn0)); s[nt][0] = p; rs0 += p;
            p = tf32r(__expf(s[nt][1] - mn0)); s[nt][1] = p; rs0 += p;
            p = tf32r(__expf(s[nt][2] - mn1)); s[nt][2] = p; rs1 += p;
            p = tf32r(__expf(s[nt][3] - mn1)); s[nt][3] = p; rs1 += p;
        }
        rs0 += __shfl_xor_sync(0xffffffffu, rs0, 1);
        rs0 += __shfl_xor_sync(0xffffffffu, rs0, 2);
        rs1 += __shfl_xor_sync(0xffffffffu, rs1, 1);
        rs1 += __shfl_xor_sync(0xffffffffu, rs1, 2);
        l0 = l0 * c0 + rs0;
        l1 = l1 * c1 + rs1;
#pragma unroll
        for (int nt = 0; nt < 8; nt++) {
            o[nt][0] *= c0; o[nt][1] *= c0;
            o[nt][2] *= c1; o[nt][3] *= c1;
        }

        // ---- O += P V : P C-frag -> A-frag via quad shuffles; LDS.64 V frags ----
        const int src1 = (lane & ~3) | (g >> 1);
        const int src2 = src1 + 2;
        const bool odd = (g & 1) != 0;
#pragma unroll
        for (int kt = 0; kt < 8; kt++) {
            float x0 = __shfl_sync(0xffffffffu, s[kt][0], src1);
            float x1 = __shfl_sync(0xffffffffu, s[kt][1], src1);
            float y0 = __shfl_sync(0xffffffffu, s[kt][2], src1);
            float y1 = __shfl_sync(0xffffffffu, s[kt][3], src1);
            float z0 = __shfl_sync(0xffffffffu, s[kt][0], src2);
            float z1 = __shfl_sync(0xffffffffu, s[kt][1], src2);
            float w0 = __shfl_sync(0xffffffffu, s[kt][2], src2);
            float w1 = __shfl_sync(0xffffffffu, s[kt][3], src2);
            float a[4];
            a[0] = odd ? x1 : x0;
            a[1] = odd ? y1 : y0;
            a[2] = odd ? z1 : z0;
            a[3] = odd ? w1 : w0;

#pragma unroll
            for (int nt = 0; nt < 8; nt++) {
                uint2 vv = *(const uint2*)(smu + 12288 + ((nt * 8 + kt) * 64) + lane * 2);
                mma_f(o[nt], a, __uint_as_float(vv.x), __uint_as_float(vv.y));
            }
        }
    }

    // ---- normalize + store [B,H,T,HD] ----
    float inv0 = 1.f / l0, inv1 = 1.f / l1;
    float* ob = ao + ((size_t)bh * NT + q0 + warp * 16) * NHD;
#pragma unroll
    for (int nt = 0; nt < 8; nt++) {
        int col = nt * 8 + 2 * g;
        *(float2*)(ob + (size_t)r * NHD + col) =
            make_float2(o[nt][0] * inv0, o[nt][1] * inv0);
        *(float2*)(ob + (size_t)(r + 8) * NHD + col) =
            make_float2(o[nt][2] * inv1, o[nt][3] * inv1);
    }
}

// ---------------------------------------------------------------------------
extern "C" void kernel_launch(void* const* d_in, const int* in_sizes, int n_in,
                              void* d_out, int out_size)
{
    const float* q  = (const float*)d_in[0];
    const float* k  = (const float*)d_in[1];
    const float* v  = (const float*)d_in[2];
    const float* Wq = (const float*)d_in[3];
    const float* bq = (const float*)d_in[4];
    const float* Wk = (const float*)d_in[5];
    const float* bk = (const float*)d_in[6];
    const float* Wv = (const float*)d_in[7];
    const float* bv = (const float*)d_in[8];
    const float* Wo = (const float*)d_in[9];
    const float* bo = (const float*)d_in[10];
    float* out = (float*)d_out;

    float *pq, *pkt, *pv, *po;
    cudaGetSymbolAddress((void**)&pq,  g_q);
    cudaGetSymbolAddress((void**)&pkt, g_kt);
    cudaGetSymbolAddress((void**)&pv,  g_v);
    cudaGetSymbolAddress((void**)&po,  g_o);

    const int gemm_smem = 65536;
    cudaFuncSetAttribute(gemm_qkv, cudaFuncAttributeMaxDynamicSharedMemorySize, gemm_smem);
    cudaFuncSetAttribute(gemm_out, cudaFuncAttributeMaxDynamicSharedMemorySize, gemm_smem);

    // One fused launch for all three input projections (1536 CTAs -> good wave fill).
    gemm_qkv<<<dim3(24, 64), 256, gemm_smem>>>(q, k, v, Wq, bq, Wk, bk, Wv, bv,
                                               pq, pkt, pv);

    const int attn_smem = 16384 * 4;   // 65,536 B -> 2 CTAs/SM
    cudaFuncSetAttribute(attn_mma, cudaFuncAttributeMaxDynamicSharedMemorySize, attn_smem);
    attn_mma<<<dim3(NT / 128, NB * NH), 256, attn_smem>>>(pq, pkt, pv, po);

    gemm_out<<<dim3(8, 64), 256, gemm_smem>>>(po, Wo, bo, out);
}

// round 15
// speedup vs baseline: 1.8215x; 1.0161x over previous
#include <cuda_runtime.h>
#include <cstdint>

#define NB 4
#define NT 2048
#define ND 1024
#define NH 16
#define NHD 64
#define NM (NB*NT)   // 8192 rows

// Scratch (allocation-free rule: __device__ globals).
__device__ float g_q [NB*NH*NT*NHD];   // [B,H,T,HD]
__device__ float g_kt[NB*NH*NHD*NT];   // [B,H,HD,T]  (K projected + transposed)
__device__ float g_v [NB*NH*NT*NHD];   // [B,H,T,HD]
__device__ float g_o [NB*NH*NT*NHD];   // [B,H,T,HD] attention output

__device__ __forceinline__ unsigned f2tf(float f) {
    unsigned u;
    asm("cvt.rna.tf32.f32 %0, %1;" : "=r"(u) : "f"(f));
    return u;
}
__device__ __forceinline__ float tf32r(float f) { return __uint_as_float(f2tf(f)); }

__device__ __forceinline__ void mma_tf32(float c[4], const unsigned a[4], const unsigned b[2]) {
    asm volatile(
        "mma.sync.aligned.m16n8k8.row.col.f32.tf32.tf32.f32 "
        "{%0,%1,%2,%3}, {%4,%5,%6,%7}, {%8,%9}, {%0,%1,%2,%3};"
        : "+f"(c[0]), "+f"(c[1]), "+f"(c[2]), "+f"(c[3])
        : "r"(a[0]), "r"(a[1]), "r"(a[2]), "r"(a[3]), "r"(b[0]), "r"(b[1]));
}
__device__ __forceinline__ void mma_f(float c[4], const float a[4], const float b0, const float b1) {
    asm volatile(
        "mma.sync.aligned.m16n8k8.row.col.f32.tf32.tf32.f32 "
        "{%0,%1,%2,%3}, {%4,%5,%6,%7}, {%8,%9}, {%0,%1,%2,%3};"
        : "+f"(c[0]), "+f"(c[1]), "+f"(c[2]), "+f"(c[3])
        : "r"(__float_as_uint(a[0])), "r"(__float_as_uint(a[1])),
          "r"(__float_as_uint(a[2])), "r"(__float_as_uint(a[3])),
          "r"(__float_as_uint(b0)),   "r"(__float_as_uint(b1)));
}

// ---------------------------------------------------------------------------
// GEMM core, K-tile 16 (32 KB smem double-buffered -> 2 CTAs/SM at <=128 regs).
// Per stage: A 128x16, W 128x16 in mma fragment order. 64 stages.
// ---------------------------------------------------------------------------
struct GemmCore {
    unsigned* As;   // 2 bufs x 2048 u32
    unsigned* Ws;   // 2 bufs x 2048 u32
    int tid, lane, wm, wn, bm, bn;
    float acc[4][4][4];
    float4 ar[2], wr[2];

    __device__ __forceinline__ void init(unsigned* sh, int bm_, int bn_) {
        As = sh; Ws = sh + 4096;
        tid = threadIdx.x; lane = tid & 31;
        int warp = tid >> 5;
        wm = warp & 1; wn = warp >> 1;
        bm = bm_; bn = bn_;
#pragma unroll
        for (int mi = 0; mi < 4; mi++)
#pragma unroll
            for (int nj = 0; nj < 4; nj++)
#pragma unroll
                for (int r = 0; r < 4; r++) acc[mi][nj][r] = 0.f;
    }

    template<int AMODE>
    __device__ __forceinline__ void ldg(const float* __restrict__ A,
                                        const float* __restrict__ W, int s) {
#pragma unroll
        for (int l = 0; l < 2; l++) {
            int idx = l * 256 + tid;
            int row = idx >> 2;          // 0..127
            int kq  = idx & 3;           // float4 within 16-wide k stage
            int kg  = s * 16 + kq * 4;
            if (AMODE == 0) {
                ar[l] = *(const float4*)(A + (size_t)(bm + row) * ND + kg);
            } else {
                int m  = bm + row;
                int b_ = m >> 11, t_ = m & (NT - 1);
                int h_ = kg >> 6, hd = kg & 63;
                ar[l] = *(const float4*)(A + (((size_t)(b_ * NH + h_) * NT + t_) * NHD + hd));
            }
            wr[l] = *(const float4*)(W + (size_t)(bn + row) * ND + kg);
        }
    }

    __device__ __forceinline__ void sts(int buf) {
        unsigned* ab = As + buf * 2048;
        unsigned* wb = Ws + buf * 2048;
#pragma unroll
        for (int l = 0; l < 2; l++) {
            int idx = l * 256 + tid;
            int row = idx >> 2;
            int kq  = idx & 3;
            {   // A tile (mt = row/16, kt = kq/2), frag addr = lane*4 + reg
                unsigned* p = ab + (((row >> 4) * 2 + (kq >> 1)) << 7);
                int reg = ((kq & 1) << 1) + ((row >> 3) & 1);
                int lb  = (row & 7) * 4;
                p[(lb + 0) * 4 + reg] = f2tf(ar[l].x);
                p[(lb + 1) * 4 + reg] = f2tf(ar[l].y);
                p[(lb + 2) * 4 + reg] = f2tf(ar[l].z);
                p[(lb + 3) * 4 + reg] = f2tf(ar[l].w);
            }
            {   // W tile (nt = row/8, kt = kq/2), frag addr = lane*2 + reg
                unsigned* p = wb + (((row >> 3) * 2 + (kq >> 1)) << 6);
                int reg = (kq & 1);
                int lb  = (row & 7) * 4;
                p[(lb + 0) * 2 + reg] = f2tf(wr[l].x);
                p[(lb + 1) * 2 + reg] = f2tf(wr[l].y);
                p[(lb + 2) * 2 + reg] = f2tf(wr[l].z);
                p[(lb + 3) * 2 + reg] = f2tf(wr[l].w);
            }
        }
    }

    __device__ __forceinline__ void compute(int buf) {
        const unsigned* ab = As + buf * 2048;
        const unsigned* wb = Ws + buf * 2048;
#pragma unroll
        for (int kt = 0; kt < 2; kt++) {
            unsigned af[4][4];
#pragma unroll
            for (int mi = 0; mi < 4; mi++) {
                uint4 t = *(const uint4*)(ab + ((((wm * 4 + mi) * 2 + kt)) << 7) + (lane << 2));
                af[mi][0] = t.x; af[mi][1] = t.y; af[mi][2] = t.z; af[mi][3] = t.w;
            }
            unsigned bf[4][2];
#pragma unroll
            for (int nj = 0; nj < 4; nj++) {
                uint2 t = *(const uint2*)(wb + ((((wn * 4 + nj) * 2 + kt)) << 6) + (lane << 1));
                bf[nj][0] = t.x; bf[nj][1] = t.y;
            }
#pragma unroll
            for (int mi = 0; mi < 4; mi++)
#pragma unroll
                for (int nj = 0; nj < 4; nj++)
                    mma_tf32(acc[mi][nj], af[mi], bf[nj]);
        }
    }

    // OMODE: 0 -> [B,H,T,HD]; 1 -> [B,H,HD,T]; 2 -> row-major [M,N]
    template<int OMODE>
    __device__ __forceinline__ void epilogue(const float* __restrict__ bias,
                                             float* __restrict__ Cout) {
#pragma unroll
        for (int nj = 0; nj < 4; nj++) {
            int col = bn + (wn * 4 + nj) * 8 + (lane & 3) * 2;
            float b0 = bias[col], b1 = bias[col + 1];
#pragma unroll
            for (int mi = 0; mi < 4; mi++) {
                int row = bm + (wm * 4 + mi) * 16 + (lane >> 2);
                float v00 = acc[mi][nj][0] + b0, v01 = acc[mi][nj][1] + b1;
                float v10 = acc[mi][nj][2] + b0, v11 = acc[mi][nj][3] + b1;
                if (OMODE == 2) {
                    *(float2*)(Cout + (size_t)row * ND + col)       = make_float2(v00, v01);
                    *(float2*)(Cout + (size_t)(row + 8) * ND + col) = make_float2(v10, v11);
                } else if (OMODE == 0) {
                    int b_ = row >> 11, t_ = row & (NT - 1);
                    int h_ = col >> 6, hd = col & 63;
                    float* p = Cout + (((size_t)(b_ * NH + h_) * NT + t_) * NHD + hd);
                    *(float2*)p             = make_float2(v00, v01);
                    *(float2*)(p + 8 * NHD) = make_float2(v10, v11);
                } else { // OMODE 1: [B,H,HD,T]
                    int b_ = row >> 11, t_ = row & (NT - 1);
                    int h_ = col >> 6, hd = col & 63;
                    float* p = Cout + (((size_t)(b_ * NH + h_) * NHD + hd) * NT + t_);
                    p[0]      = v00;
                    p[NT]     = v01;
                    p[8]      = v10;
                    p[NT + 8] = v11;
                }
            }
        }
    }
};

template<int AMODE>
__device__ __forceinline__ void gemm_body(GemmCore& gc, const float* A, const float* W) {
    gc.ldg<AMODE>(A, W, 0);
    gc.sts(0);
    __syncthreads();
    for (int s = 0; s < 64; s++) {
        int buf = s & 1;
        if (s < 63) gc.ldg<AMODE>(A, W, s + 1);
        gc.compute(buf);
        if (s < 63) gc.sts(buf ^ 1);
        __syncthreads();
    }
}

// Fused Q/K/V projection: grid (24, 64); blockIdx.x = which*8 + bn_idx.
__global__ __launch_bounds__(256, 2)
void gemm_qkv(const float* __restrict__ qin, const float* __restrict__ kin,
              const float* __restrict__ vin,
              const float* __restrict__ Wq, const float* __restrict__ bq,
              const float* __restrict__ Wk, const float* __restrict__ bk,
              const float* __restrict__ Wv, const float* __restrict__ bv,
              float* __restrict__ oq, float* __restrict__ okt, float* __restrict__ ov)
{
    extern __shared__ unsigned sh[];
    const int which = blockIdx.x >> 3;
    const int bn = (blockIdx.x & 7) * 128;
    const int bm = blockIdx.y * 128;

    GemmCore gc;
    gc.init(sh, bm, bn);
    if (which == 0) {
        gemm_body<0>(gc, qin, Wq);
        gc.epilogue<0>(bq, oq);
    } else if (which == 1) {
        gemm_body<0>(gc, kin, Wk);
        gc.epilogue<1>(bk, okt);     // K proj + transpose fused
    } else {
        gemm_body<0>(gc, vin, Wv);
        gc.epilogue<0>(bv, ov);
    }
}

// Output projection: A gathered from head layout, row-major out.
__global__ __launch_bounds__(256, 2)
void gemm_out(const float* __restrict__ A, const float* __restrict__ W,
              const float* __restrict__ bias, float* __restrict__ Cout)
{
    extern __shared__ unsigned sh[];
    GemmCore gc;
    gc.init(sh, blockIdx.y * 128, blockIdx.x * 128);
    gemm_body<1>(gc, A, W);
    gc.epilogue<2>(bias, Cout);
}

// ---------------------------------------------------------------------------
// Flash attention v9 (unchanged from passing R14): single-chain pure-tf32 S.
// 256 threads = 8 warps; CTA = 128 queries; warp owns 16 rows (mt = warp).
// smem (u32), 64 KB -> 2 CTAs/SM:
//  QH [0,8192)      tile(mt*8+kt)*128: uint4/lane = A-frag
//  KH [8192,12288)  tile(nt*8+kt)*64 : uint2/lane
//  VH [12288,16384) tile(nt*8+kt)*64 : uint2/lane
// ---------------------------------------------------------------------------
__global__ __launch_bounds__(256, 2)
void attn_mma(const float* __restrict__ qp, const float* __restrict__ ktp,
              const float* __restrict__ vp, float* __restrict__ ao)
{
    extern __shared__ unsigned smu[];

    const int tid  = threadIdx.x;
    const int lane = tid & 31;
    const int warp = tid >> 5;
    const int r    = lane >> 2;          // 0..7
    const int g    = lane & 3;           // 0..3
    const int bh   = blockIdx.y;
    const int q0   = blockIdx.x * 128;

    const float* qb = qp  + ((size_t)bh * NT + q0) * NHD;
    const float* kb = ktp + (size_t)bh * NHD * NT;
    const float* vb = vp  + (size_t)bh * NT * NHD;

    // ---- Stage Q once in A-frag order (hi only). 2048 float4, 8 iters. ----
#pragma unroll
    for (int i = 0; i < 8; i++) {
        int idx = i * 256 + tid;
        int uu = idx & 31, blk = idx >> 5;          // warp spans 8 rows x 4 f4
        int qrow = (uu >> 2) + (blk & 15) * 8;      // 0..127
        int f4   = (uu & 3) + (blk >> 4) * 4;       // 0..15
        float4 x = *(const float4*)(qb + qrow * NHD + f4 * 4);
        float xe[4] = {x.x, x.y, x.z, x.w};
        int mt = qrow >> 4;
        int lb = (qrow & 7) * 4;
        int rr = (qrow >> 3) & 1;
#pragma unroll
        for (int e = 0; e < 4; e++) {
            int hd = f4 * 4 + e;
            int ad = ((mt * 8 + (hd >> 3)) * 128) + (lb + (hd & 3)) * 4
                     + ((hd >> 2) & 1) * 2 + rr;
            smu[ad] = f2tf(xe[e]);
        }
    }

    float o[8][4];
#pragma unroll
    for (int nt = 0; nt < 8; nt++)
#pragma unroll
        for (int c = 0; c < 4; c++) o[nt][c] = 0.f;
    float m0 = -1e30f, m1 = -1e30f, l0 = 0.f, l1 = 0.f;

    for (int t0 = 0; t0 < NT; t0 += 64) {
        __syncthreads();   // prev compute done before restaging (covers Q on iter 0)
        // ---- Stage K and V (hi only) in B-frag order. ----
#pragma unroll
        for (int i = 0; i < 4; i++) {
            int idx = i * 256 + tid;
            int uu = idx & 31, blk = idx >> 5;      // 0..31
            int row = (uu >> 2) + (blk & 7) * 8;    // 0..63
            int f4  = (uu & 3) + (blk >> 3) * 4;    // 0..15
            {   // K: row = hd, f4 indexes keys
                float4 x = *(const float4*)(kb + (size_t)row * NT + t0 + f4 * 4);
                float xe[4] = {x.x, x.y, x.z, x.w};
                int kt = row >> 3;
                int reg = (row >> 2) & 1;
                int lh = row & 3;
#pragma unroll
                for (int e = 0; e < 4; e++) {
                    int key = f4 * 4 + e;
                    int ad = 8192 + (((key >> 3) * 8 + kt) * 64)
                             + ((key & 7) * 4 + lh) * 2 + reg;
                    smu[ad] = f2tf(xe[e]);
                }
            }
            {   // V: row = key, f4 indexes hd
                float4 y = *(const float4*)(vb + (size_t)(t0 + row) * NHD + f4 * 4);
                float ye[4] = {y.x, y.y, y.z, y.w};
                int kt = row >> 3;
                int reg = (row >> 2) & 1;
                int lk = row & 3;
#pragma unroll
                for (int e = 0; e < 4; e++) {
                    int hd = f4 * 4 + e;
                    int ad = 12288 + (((hd >> 3) * 8 + kt) * 64)
                             + ((hd & 7) * 4 + lk) * 2 + reg;
                    smu[ad] = f2tf(ye[e]);
                }
            }
        }
        __syncthreads();

        // ---- S = Q K^T : single chain (pure tf32) ----
        float s[8][4];
#pragma unroll
        for (int nt = 0; nt < 8; nt++)
#pragma unroll
            for (int c = 0; c < 4; c++) s[nt][c] = 0.f;

#pragma unroll
        for (int kt = 0; kt < 8; kt++) {
            uint4 qh4 = *(const uint4*)(smu + (warp * 8 + kt) * 128 + lane * 4);
            float ah[4] = {__uint_as_float(qh4.x), __uint_as_float(qh4.y),
                           __uint_as_float(qh4.z), __uint_as_float(qh4.w)};
#pragma unroll
            for (int half = 0; half < 2; half++) {
                uint2 kk[4];
#pragma unroll
                for (int j = 0; j < 4; j++)
                    kk[j] = *(const uint2*)(smu + 8192
                              + (((half * 4 + j) * 8 + kt) * 64) + lane * 2);
#pragma unroll
                for (int j = 0; j < 4; j++)
                    mma_f(s[half*4+j], ah, __uint_as_float(kk[j].x), __uint_as_float(kk[j].y));
            }
        }

        // ---- online softmax (rows r, r+8; quad-wide reductions) ----
        float mx0 = -1e30f, mx1 = -1e30f;
#pragma unroll
        for (int nt = 0; nt < 8; nt++) {
            s[nt][0] *= 0.125f; s[nt][1] *= 0.125f;
            s[nt][2] *= 0.125f; s[nt][3] *= 0.125f;
            mx0 = fmaxf(mx0, fmaxf(s[nt][0], s[nt][1]));
            mx1 = fmaxf(mx1, fmaxf(s[nt][2], s[nt][3]));
        }
        mx0 = fmaxf(mx0, __shfl_xor_sync(0xffffffffu, mx0, 1));
        mx0 = fmaxf(mx0, __shfl_xor_sync(0xffffffffu, mx0, 2));
        mx1 = fmaxf(mx1, __shfl_xor_sync(0xffffffffu, mx1, 1));
        mx1 = fmaxf(mx1, __shfl_xor_sync(0xffffffffu, mx1, 2));

        float mn0 = fmaxf(m0, mx0), mn1 = fmaxf(m1, mx1);
        float c0 = __expf(m0 - mn0), c1 = __expf(m1 - mn1);
        m0 = mn0; m1 = mn1;

        float rs0 = 0.f, rs1 = 0.f;
#pragma unroll
        for (int nt = 0; nt < 8; nt++) {
            float p;
            p = tf32r(__expf(s[nt][0] - mn0)); s[nt][0] = p; rs0 += p;
            p = tf32r(__expf(s[nt][1] - mn0)); s[nt][1] = p; rs0 += p;
            p = tf32r(__expf(s[nt][2] - mn1)); s[nt][2] = p; rs1 += p;
            p = tf32r(__expf(s[nt][3] - mn1)); s[nt][3] = p; rs1 += p;
        }
        rs0 += __shfl_xor_sync(0xffffffffu, rs0, 1);
        rs0 += __shfl_xor_sync(0xffffffffu, rs0, 2);
        rs1 += __shfl_xor_sync(0xffffffffu, rs1, 1);
        rs1 += __shfl_xor_sync(0xffffffffu, rs1, 2);
        l0 = l0 * c0 + rs0;
        l1 = l1 * c1 + rs1;
#pragma unroll
        for (int nt = 0; nt < 8; nt++) {
            o[nt][0] *= c0; o[nt][1] *= c0;
            o[nt][2] *= c1; o[nt][3] *= c1;
        }

        // ---- O += P V : P C-frag -> A-frag via quad shuffles; LDS.64 V frags ----
        const int src1 = (lane & ~3) | (g >> 1);
        const int src2 = src1 + 2;
        const bool odd = (g & 1) != 0;
#pragma unroll
        for (int kt = 0; kt < 8; kt++) {
            float x0 = __shfl_sync(0xffffffffu, s[kt][0], src1);
            float x1 = __shfl_sync(0xffffffffu, s[kt][1], src1);
            float y0 = __shfl_sync(0xffffffffu, s[kt][2], src1);
            float y1 = __shfl_sync(0xffffffffu, s[kt][3], src1);
            float z0 = __shfl_sync(0xffffffffu, s[kt][0], src2);
            float z1 = __shfl_sync(0xffffffffu, s[kt][1], src2);
            float w0 = __shfl_sync(0xffffffffu, s[kt][2], src2);
            float w1 = __shfl_sync(0xffffffffu, s[kt][3], src2);
            float a[4];
            a[0] = odd ? x1 : x0;
            a[1] = odd ? y1 : y0;
            a[2] = odd ? z1 : z0;
            a[3] = odd ? w1 : w0;

#pragma unroll
            for (int nt = 0; nt < 8; nt++) {
                uint2 vv = *(const uint2*)(smu + 12288 + ((nt * 8 + kt) * 64) + lane * 2);
                mma_f(o[nt], a, __uint_as_float(vv.x), __uint_as_float(vv.y));
            }
        }
    }

    // ---- normalize + store [B,H,T,HD] ----
    float inv0 = 1.f / l0, inv1 = 1.f / l1;
    float* ob = ao + ((size_t)bh * NT + q0 + warp * 16) * NHD;
#pragma unroll
    for (int nt = 0; nt < 8; nt++) {
        int col = nt * 8 + 2 * g;
        *(float2*)(ob + (size_t)r * NHD + col) =
            make_float2(o[nt][0] * inv0, o[nt][1] * inv0);
        *(float2*)(ob + (size_t)(r + 8) * NHD + col) =
            make_float2(o[nt][2] * inv1, o[nt][3] * inv1);
    }
}

// ---------------------------------------------------------------------------
extern "C" void kernel_launch(void* const* d_in, const int* in_sizes, int n_in,
                              void* d_out, int out_size)
{
    const float* q  = (const float*)d_in[0];
    const float* k  = (const float*)d_in[1];
    const float* v  = (const float*)d_in[2];
    const float* Wq = (const float*)d_in[3];
    const float* bq = (const float*)d_in[4];
    const float* Wk = (const float*)d_in[5];
    const float* bk = (const float*)d_in[6];
    const float* Wv = (const float*)d_in[7];
    const float* bv = (const float*)d_in[8];
    const float* Wo = (const float*)d_in[9];
    const float* bo = (const float*)d_in[10];
    float* out = (float*)d_out;

    float *pq, *pkt, *pv, *po;
    cudaGetSymbolAddress((void**)&pq,  g_q);
    cudaGetSymbolAddress((void**)&pkt, g_kt);
    cudaGetSymbolAddress((void**)&pv,  g_v);
    cudaGetSymbolAddress((void**)&po,  g_o);

    const int gemm_smem = 32768;   // 2 x (8KB A + 8KB W)
    cudaFuncSetAttribute(gemm_qkv, cudaFuncAttributeMaxDynamicSharedMemorySize, gemm_smem);
    cudaFuncSetAttribute(gemm_out, cudaFuncAttributeMaxDynamicSharedMemorySize, gemm_smem);

    // One fused launch for all three input projections (1536 CTAs).
    gemm_qkv<<<dim3(24, 64), 256, gemm_smem>>>(q, k, v, Wq, bq, Wk, bk, Wv, bv,
                                               pq, pkt, pv);

    const int attn_smem = 16384 * 4;   // 65,536 B -> 2 CTAs/SM
    cudaFuncSetAttribute(attn_mma, cudaFuncAttributeMaxDynamicSharedMemorySize, attn_smem);
    attn_mma<<<dim3(NT / 128, NB * NH), 256, attn_smem>>>(pq, pkt, pv, po);

    gemm_out<<<dim3(8, 64), 256, gemm_smem>>>(po, Wo, bo, out);
}

// round 16
// speedup vs baseline: 1.9724x; 1.0829x over previous
#include <cuda_runtime.h>
#include <cstdint>

#define NB 4
#define NT 2048
#define ND 1024
#define NH 16
#define NHD 64
#define NM (NB*NT)   // 8192 rows

// Scratch (allocation-free rule: __device__ globals).
__device__ float g_q [NB*NH*NT*NHD];   // [B,H,T,HD]
__device__ float g_kt[NB*NH*NHD*NT];   // [B,H,HD,T]  (K projected + transposed)
__device__ float g_v [NB*NH*NT*NHD];   // [B,H,T,HD]
__device__ float g_o [NB*NH*NT*NHD];   // [B,H,T,HD] attention output

__device__ __forceinline__ unsigned f2tf(float f) {
    unsigned u;
    asm("cvt.rna.tf32.f32 %0, %1;" : "=r"(u) : "f"(f));
    return u;
}
__device__ __forceinline__ float tf32r(float f) { return __uint_as_float(f2tf(f)); }

__device__ __forceinline__ void mma_tf32(float c[4], const unsigned a[4], const unsigned b[2]) {
    asm volatile(
        "mma.sync.aligned.m16n8k8.row.col.f32.tf32.tf32.f32 "
        "{%0,%1,%2,%3}, {%4,%5,%6,%7}, {%8,%9}, {%0,%1,%2,%3};"
        : "+f"(c[0]), "+f"(c[1]), "+f"(c[2]), "+f"(c[3])
        : "r"(a[0]), "r"(a[1]), "r"(a[2]), "r"(a[3]), "r"(b[0]), "r"(b[1]));
}
__device__ __forceinline__ void mma_f(float c[4], const float a[4], const float b0, const float b1) {
    asm volatile(
        "mma.sync.aligned.m16n8k8.row.col.f32.tf32.tf32.f32 "
        "{%0,%1,%2,%3}, {%4,%5,%6,%7}, {%8,%9}, {%0,%1,%2,%3};"
        : "+f"(c[0]), "+f"(c[1]), "+f"(c[2]), "+f"(c[3])
        : "r"(__float_as_uint(a[0])), "r"(__float_as_uint(a[1])),
          "r"(__float_as_uint(a[2])), "r"(__float_as_uint(a[3])),
          "r"(__float_as_uint(b0)),   "r"(__float_as_uint(b1)));
}

// ---------------------------------------------------------------------------
// GEMM core, K-tile 16, 2 CTAs/SM. Staging stores use element ROTATION to cut
// STS bank conflicts (A: 8-way -> 2-way, W: 4-way -> 2-way). Data placement
// identical to R15, so results are bit-identical.
// ---------------------------------------------------------------------------
struct GemmCore {
    unsigned* As;   // 2 bufs x 2048 u32
    unsigned* Ws;   // 2 bufs x 2048 u32
    int tid, lane, wm, wn, bm, bn;
    float acc[4][4][4];
    float4 ar[2], wr[2];

    __device__ __forceinline__ void init(unsigned* sh, int bm_, int bn_) {
        As = sh; Ws = sh + 4096;
        tid = threadIdx.x; lane = tid & 31;
        int warp = tid >> 5;
        wm = warp & 1; wn = warp >> 1;
        bm = bm_; bn = bn_;
#pragma unroll
        for (int mi = 0; mi < 4; mi++)
#pragma unroll
            for (int nj = 0; nj < 4; nj++)
#pragma unroll
                for (int r = 0; r < 4; r++) acc[mi][nj][r] = 0.f;
    }

    template<int AMODE>
    __device__ __forceinline__ void ldg(const float* __restrict__ A,
                                        const float* __restrict__ W, int s) {
#pragma unroll
        for (int l = 0; l < 2; l++) {
            int idx = l * 256 + tid;
            int row = idx >> 2;          // 0..127
            int kq  = idx & 3;           // float4 within 16-wide k stage
            int kg  = s * 16 + kq * 4;
            if (AMODE == 0) {
                ar[l] = *(const float4*)(A + (size_t)(bm + row) * ND + kg);
            } else {
                int m  = bm + row;
                int b_ = m >> 11, t_ = m & (NT - 1);
                int h_ = kg >> 6, hd = kg & 63;
                ar[l] = *(const float4*)(A + (((size_t)(b_ * NH + h_) * NT + t_) * NHD + hd));
            }
            wr[l] = *(const float4*)(W + (size_t)(bn + row) * ND + kg);
        }
    }

    __device__ __forceinline__ void sts(int buf) {
        unsigned* ab = As + buf * 2048;
        unsigned* wb = Ws + buf * 2048;
#pragma unroll
        for (int l = 0; l < 2; l++) {
            int idx = l * 256 + tid;
            int row = idx >> 2;
            int kq  = idx & 3;
            float ae[4] = {ar[l].x, ar[l].y, ar[l].z, ar[l].w};
            float we[4] = {wr[l].x, wr[l].y, wr[l].z, wr[l].w};
            {   // A tile (mt = row/16, kt = kq/2), frag addr = lane*4 + reg
                unsigned* p = ab + (((row >> 4) * 2 + (kq >> 1)) << 7);
                int reg = ((kq & 1) << 1) + ((row >> 3) & 1);
                int lb  = (row & 7) * 4;
                int rotA = (row >> 1) & 3;
#pragma unroll
                for (int e = 0; e < 4; e++) {
                    int ee = (e + rotA) & 3;
                    p[(lb + ee) * 4 + reg] = f2tf(ae[ee]);
                }
            }
            {   // W tile (nt = row/8, kt = kq/2), frag addr = lane*2 + reg
                unsigned* p = wb + (((row >> 3) * 2 + (kq >> 1)) << 6);
                int reg = (kq & 1);
                int lb  = (row & 7) * 4;
                int rotW = ((row >> 2) & 1) * 2;
#pragma unroll
                for (int e = 0; e < 4; e++) {
                    int ee = (e + rotW) & 3;
                    p[(lb + ee) * 2 + reg] = f2tf(we[ee]);
                }
            }
        }
    }

    __device__ __forceinline__ void compute(int buf) {
        const unsigned* ab = As + buf * 2048;
        const unsigned* wb = Ws + buf * 2048;
#pragma unroll
        for (int kt = 0; kt < 2; kt++) {
            unsigned af[4][4];
#pragma unroll
            for (int mi = 0; mi < 4; mi++) {
                uint4 t = *(const uint4*)(ab + ((((wm * 4 + mi) * 2 + kt)) << 7) + (lane << 2));
                af[mi][0] = t.x; af[mi][1] = t.y; af[mi][2] = t.z; af[mi][3] = t.w;
            }
            unsigned bf[4][2];
#pragma unroll
            for (int nj = 0; nj < 4; nj++) {
                uint2 t = *(const uint2*)(wb + ((((wn * 4 + nj) * 2 + kt)) << 6) + (lane << 1));
                bf[nj][0] = t.x; bf[nj][1] = t.y;
            }
#pragma unroll
            for (int mi = 0; mi < 4; mi++)
#pragma unroll
                for (int nj = 0; nj < 4; nj++)
                    mma_tf32(acc[mi][nj], af[mi], bf[nj]);
        }
    }

    // OMODE: 0 -> [B,H,T,HD]; 1 -> [B,H,HD,T]; 2 -> row-major [M,N]
    template<int OMODE>
    __device__ __forceinline__ void epilogue(const float* __restrict__ bias,
                                             float* __restrict__ Cout) {
#pragma unroll
        for (int nj = 0; nj < 4; nj++) {
            int col = bn + (wn * 4 + nj) * 8 + (lane & 3) * 2;
            float b0 = bias[col], b1 = bias[col + 1];
#pragma unroll
            for (int mi = 0; mi < 4; mi++) {
                int row = bm + (wm * 4 + mi) * 16 + (lane >> 2);
                float v00 = acc[mi][nj][0] + b0, v01 = acc[mi][nj][1] + b1;
                float v10 = acc[mi][nj][2] + b0, v11 = acc[mi][nj][3] + b1;
                if (OMODE == 2) {
                    *(float2*)(Cout + (size_t)row * ND + col)       = make_float2(v00, v01);
                    *(float2*)(Cout + (size_t)(row + 8) * ND + col) = make_float2(v10, v11);
                } else if (OMODE == 0) {
                    int b_ = row >> 11, t_ = row & (NT - 1);
                    int h_ = col >> 6, hd = col & 63;
                    float* p = Cout + (((size_t)(b_ * NH + h_) * NT + t_) * NHD + hd);
                    *(float2*)p             = make_float2(v00, v01);
                    *(float2*)(p + 8 * NHD) = make_float2(v10, v11);
                } else { // OMODE 1: [B,H,HD,T]
                    int b_ = row >> 11, t_ = row & (NT - 1);
                    int h_ = col >> 6, hd = col & 63;
                    float* p = Cout + (((size_t)(b_ * NH + h_) * NHD + hd) * NT + t_);
                    p[0]      = v00;
                    p[NT]     = v01;
                    p[8]      = v10;
                    p[NT + 8] = v11;
                }
            }
        }
    }
};

template<int AMODE>
__device__ __forceinline__ void gemm_body(GemmCore& gc, const float* A, const float* W) {
    gc.ldg<AMODE>(A, W, 0);
    gc.sts(0);
    __syncthreads();
    for (int s = 0; s < 64; s++) {
        int buf = s & 1;
        if (s < 63) gc.ldg<AMODE>(A, W, s + 1);
        gc.compute(buf);
        if (s < 63) gc.sts(buf ^ 1);
        __syncthreads();
    }
}

// Fused Q/K/V projection: grid (24, 64); blockIdx.x = which*8 + bn_idx.
__global__ __launch_bounds__(256, 2)
void gemm_qkv(const float* __restrict__ qin, const float* __restrict__ kin,
              const float* __restrict__ vin,
              const float* __restrict__ Wq, const float* __restrict__ bq,
              const float* __restrict__ Wk, const float* __restrict__ bk,
              const float* __restrict__ Wv, const float* __restrict__ bv,
              float* __restrict__ oq, float* __restrict__ okt, float* __restrict__ ov)
{
    extern __shared__ unsigned sh[];
    const int which = blockIdx.x >> 3;
    const int bn = (blockIdx.x & 7) * 128;
    const int bm = blockIdx.y * 128;

    GemmCore gc;
    gc.init(sh, bm, bn);
    if (which == 0) {
        gemm_body<0>(gc, qin, Wq);
        gc.epilogue<0>(bq, oq);
    } else if (which == 1) {
        gemm_body<0>(gc, kin, Wk);
        gc.epilogue<1>(bk, okt);     // K proj + transpose fused
    } else {
        gemm_body<0>(gc, vin, Wv);
        gc.epilogue<0>(bv, ov);
    }
}

// Output projection: A gathered from head layout, row-major out.
__global__ __launch_bounds__(256, 2)
void gemm_out(const float* __restrict__ A, const float* __restrict__ W,
              const float* __restrict__ bias, float* __restrict__ Cout)
{
    extern __shared__ unsigned sh[];
    GemmCore gc;
    gc.init(sh, blockIdx.y * 128, blockIdx.x * 128);
    gemm_body<1>(gc, A, W);
    gc.epilogue<2>(bias, Cout);
}

// ---------------------------------------------------------------------------
// Flash attention v10: R14's v9 + rotated staging stores (Q: 8way->2way,
// K/V: 4way->conflict-free). Data placement and math bit-identical to R14/R15.
// 256 threads = 8 warps; CTA = 128 queries; warp owns 16 rows.
// smem (u32), 64 KB -> 2 CTAs/SM:
//  QH [0,8192)      tile(mt*8+kt)*128: uint4/lane = A-frag
//  KH [8192,12288)  tile(nt*8+kt)*64 : uint2/lane
//  VH [12288,16384) tile(nt*8+kt)*64 : uint2/lane
// ---------------------------------------------------------------------------
__global__ __launch_bounds__(256, 2)
void attn_mma(const float* __restrict__ qp, const float* __restrict__ ktp,
              const float* __restrict__ vp, float* __restrict__ ao)
{
    extern __shared__ unsigned smu[];

    const int tid  = threadIdx.x;
    const int lane = tid & 31;
    const int warp = tid >> 5;
    const int r    = lane >> 2;          // 0..7
    const int g    = lane & 3;           // 0..3
    const int bh   = blockIdx.y;
    const int q0   = blockIdx.x * 128;

    const float* qb = qp  + ((size_t)bh * NT + q0) * NHD;
    const float* kb = ktp + (size_t)bh * NHD * NT;
    const float* vb = vp  + (size_t)bh * NT * NHD;

    // ---- Stage Q once in A-frag order (hi only), rotated stores. ----
#pragma unroll
    for (int i = 0; i < 8; i++) {
        int idx = i * 256 + tid;
        int uu = idx & 31, blk = idx >> 5;          // warp spans 8 rows x 4 f4
        int qrow = (uu >> 2) + (blk & 15) * 8;      // 0..127
        int f4   = (uu & 3) + (blk >> 4) * 4;       // 0..15
        float4 x = *(const float4*)(qb + qrow * NHD + f4 * 4);
        float xe[4] = {x.x, x.y, x.z, x.w};
        int mt = qrow >> 4;
        int lb = (qrow & 7) * 4;
        int rr = (qrow >> 3) & 1;
        int rot = (qrow >> 1) & 3;
#pragma unroll
        for (int e = 0; e < 4; e++) {
            int ee = (e + rot) & 3;
            int hd = f4 * 4 + ee;
            int ad = ((mt * 8 + (hd >> 3)) * 128) + (lb + (hd & 3)) * 4
                     + ((hd >> 2) & 1) * 2 + rr;
            smu[ad] = f2tf(xe[ee]);
        }
    }

    float o[8][4];
#pragma unroll
    for (int nt = 0; nt < 8; nt++)
#pragma unroll
        for (int c = 0; c < 4; c++) o[nt][c] = 0.f;
    float m0 = -1e30f, m1 = -1e30f, l0 = 0.f, l1 = 0.f;

    for (int t0 = 0; t0 < NT; t0 += 64) {
        __syncthreads();   // prev compute done before restaging (covers Q on iter 0)
        // ---- Stage K and V (hi only) in B-frag order, rotated stores. ----
#pragma unroll
        for (int i = 0; i < 4; i++) {
            int idx = i * 256 + tid;
            int uu = idx & 31, blk = idx >> 5;      // 0..31
            int row = (uu >> 2) + (blk & 7) * 8;    // 0..63
            int f4  = (uu & 3) + (blk >> 3) * 4;    // 0..15
            int rot = uu & 3;
            {   // K: row = hd, f4 indexes keys
                float4 x = *(const float4*)(kb + (size_t)row * NT + t0 + f4 * 4);
                float xe[4] = {x.x, x.y, x.z, x.w};
                int kt = row >> 3;
                int reg = (row >> 2) & 1;
                int lh = row & 3;
#pragma unroll
                for (int e = 0; e < 4; e++) {
                    int ee = (e + rot) & 3;
                    int key = f4 * 4 + ee;
                    int ad = 8192 + (((key >> 3) * 8 + kt) * 64)
                             + ((key & 7) * 4 + lh) * 2 + reg;
                    smu[ad] = f2tf(xe[ee]);
                }
            }
            {   // V: row = key, f4 indexes hd
                float4 y = *(const float4*)(vb + (size_t)(t0 + row) * NHD + f4 * 4);
                float ye[4] = {y.x, y.y, y.z, y.w};
                int kt = row >> 3;
                int reg = (row >> 2) & 1;
                int lk = row & 3;
#pragma unroll
                for (int e = 0; e < 4; e++) {
                    int ee = (e + rot) & 3;
                    int hd = f4 * 4 + ee;
                    int ad = 12288 + (((hd >> 3) * 8 + kt) * 64)
                             + ((hd & 7) * 4 + lk) * 2 + reg;
                    smu[ad] = f2tf(ye[ee]);
                }
            }
        }
        __syncthreads();

        // ---- S = Q K^T : single chain (pure tf32) ----
        float s[8][4];
#pragma unroll
        for (int nt = 0; nt < 8; nt++)
#pragma unroll
            for (int c = 0; c < 4; c++) s[nt][c] = 0.f;

#pragma unroll
        for (int kt = 0; kt < 8; kt++) {
            uint4 qh4 = *(const uint4*)(smu + (warp * 8 + kt) * 128 + lane * 4);
            float ah[4] = {__uint_as_float(qh4.x), __uint_as_float(qh4.y),
                           __uint_as_float(qh4.z), __uint_as_float(qh4.w)};
#pragma unroll
            for (int half = 0; half < 2; half++) {
                uint2 kk[4];
#pragma unroll
                for (int j = 0; j < 4; j++)
                    kk[j] = *(const uint2*)(smu + 8192
                              + (((half * 4 + j) * 8 + kt) * 64) + lane * 2);
#pragma unroll
                for (int j = 0; j < 4; j++)
                    mma_f(s[half*4+j], ah, __uint_as_float(kk[j].x), __uint_as_float(kk[j].y));
            }
        }

        // ---- online softmax (rows r, r+8; quad-wide reductions) ----
        float mx0 = -1e30f, mx1 = -1e30f;
#pragma unroll
        for (int nt = 0; nt < 8; nt++) {
            s[nt][0] *= 0.125f; s[nt][1] *= 0.125f;
            s[nt][2] *= 0.125f; s[nt][3] *= 0.125f;
            mx0 = fmaxf(mx0, fmaxf(s[nt][0], s[nt][1]));
            mx1 = fmaxf(mx1, fmaxf(s[nt][2], s[nt][3]));
        }
        mx0 = fmaxf(mx0, __shfl_xor_sync(0xffffffffu, mx0, 1));
        mx0 = fmaxf(mx0, __shfl_xor_sync(0xffffffffu, mx0, 2));
        mx1 = fmaxf(mx1, __shfl_xor_sync(0xffffffffu, mx1, 1));
        mx1 = fmaxf(mx1, __shfl_xor_sync(0xffffffffu, mx1, 2));

        float mn0 = fmaxf(m0, mx0), mn1 = fmaxf(m1, mx1);
        float c0 = __expf(m0 - mn0), c1 = __expf(m1 - mn1);
        m0 = mn0; m1 = mn1;

        float rs0 = 0.f, rs1 = 0.f;
#pragma unroll
        for (int nt = 0; nt < 8; nt++) {
            float p;
            p = tf32r(__expf(s[nt][0] - mn0)); s[nt][0] = p; rs0 += p;
            p = tf32r(__expf(s[nt][1] - mn0)); s[nt][1] = p; rs0 += p;
            p = tf32r(__expf(s[nt][2] - mn1)); s[nt][2] = p; rs1 += p;
            p = tf32r(__expf(s[nt][3] - mn1)); s[nt][3] = p; rs1 += p;
        }
        rs0 += __shfl_xor_sync(0xffffffffu, rs0, 1);
        rs0 += __shfl_xor_sync(0xffffffffu, rs0, 2);
        rs1 += __shfl_xor_sync(0xffffffffu, rs1, 1);
        rs1 += __shfl_xor_sync(0xffffffffu, rs1, 2);
        l0 = l0 * c0 + rs0;
        l1 = l1 * c1 + rs1;
#pragma unroll
        for (int nt = 0; nt < 8; nt++) {
            o[nt][0] *= c0; o[nt][1] *= c0;
            o[nt][2] *= c1; o[nt][3] *= c1;
        }

        // ---- O += P V : P C-frag -> A-frag via quad shuffles; LDS.64 V frags ----
        const int src1 = (lane & ~3) | (g >> 1);
        const int src2 = src1 + 2;
        const bool odd = (g & 1) != 0;
#pragma unroll
        for (int kt = 0; kt < 8; kt++) {
            float x0 = __shfl_sync(0xffffffffu, s[kt][0], src1);
            float x1 = __shfl_sync(0xffffffffu, s[kt][1], src1);
            float y0 = __shfl_sync(0xffffffffu, s[kt][2], src1);
            float y1 = __shfl_sync(0xffffffffu, s[kt][3], src1);
            float z0 = __shfl_sync(0xffffffffu, s[kt][0], src2);
            float z1 = __shfl_sync(0xffffffffu, s[kt][1], src2);
            float w0 = __shfl_sync(0xffffffffu, s[kt][2], src2);
            float w1 = __shfl_sync(0xffffffffu, s[kt][3], src2);
            float a[4];
            a[0] = odd ? x1 : x0;
            a[1] = odd ? y1 : y0;
            a[2] = odd ? z1 : z0;
            a[3] = odd ? w1 : w0;

#pragma unroll
            for (int nt = 0; nt < 8; nt++) {
                uint2 vv = *(const uint2*)(smu + 12288 + ((nt * 8 + kt) * 64) + lane * 2);
                mma_f(o[nt], a, __uint_as_float(vv.x), __uint_as_float(vv.y));
            }
        }
    }

    // ---- normalize + store [B,H,T,HD] ----
    float inv0 = 1.f / l0, inv1 = 1.f / l1;
    float* ob = ao + ((size_t)bh * NT + q0 + warp * 16) * NHD;
#pragma unroll
    for (int nt = 0; nt < 8; nt++) {
        int col = nt * 8 + 2 * g;
        *(float2*)(ob + (size_t)r * NHD + col) =
            make_float2(o[nt][0] * inv0, o[nt][1] * inv0);
        *(float2*)(ob + (size_t)(r + 8) * NHD + col) =
            make_float2(o[nt][2] * inv1, o[nt][3] * inv1);
    }
}

// ---------------------------------------------------------------------------
extern "C" void kernel_launch(void* const* d_in, const int* in_sizes, int n_in,
                              void* d_out, int out_size)
{
    const float* q  = (const float*)d_in[0];
    const float* k  = (const float*)d_in[1];
    const float* v  = (const float*)d_in[2];
    const float* Wq = (const float*)d_in[3];
    const float* bq = (const float*)d_in[4];
    const float* Wk = (const float*)d_in[5];
    const float* bk = (const float*)d_in[6];
    const float* Wv = (const float*)d_in[7];
    const float* bv = (const float*)d_in[8];
    const float* Wo = (const float*)d_in[9];
    const float* bo = (const float*)d_in[10];
    float* out = (float*)d_out;

    float *pq, *pkt, *pv, *po;
    cudaGetSymbolAddress((void**)&pq,  g_q);
    cudaGetSymbolAddress((void**)&pkt, g_kt);
    cudaGetSymbolAddress((void**)&pv,  g_v);
    cudaGetSymbolAddress((void**)&po,  g_o);

    const int gemm_smem = 32768;   // 2 x (8KB A + 8KB W)
    cudaFuncSetAttribute(gemm_qkv, cudaFuncAttributeMaxDynamicSharedMemorySize, gemm_smem);
    cudaFuncSetAttribute(gemm_out, cudaFuncAttributeMaxDynamicSharedMemorySize, gemm_smem);

    // One fused launch for all three input projections (1536 CTAs).
    gemm_qkv<<<dim3(24, 64), 256, gemm_smem>>>(q, k, v, Wq, bq, Wk, bk, Wv, bv,
                                               pq, pkt, pv);

    const int attn_smem = 16384 * 4;   // 65,536 B -> 2 CTAs/SM
    cudaFuncSetAttribute(attn_mma, cudaFuncAttributeMaxDynamicSharedMemorySize, attn_smem);
    attn_mma<<<dim3(NT / 128, NB * NH), 256, attn_smem>>>(pq, pkt, pv, po);

    gemm_out<<<dim3(8, 64), 256, gemm_smem>>>(po, Wo, bo, out);
}

// round 17
// speedup vs baseline: 2.2871x; 1.1596x over previous
#include <cuda_runtime.h>
#include <cstdint>

#define NB 4
#define NT 2048
#define ND 1024
#define NH 16
#define NHD 64
#define NM (NB*NT)   // 8192 rows

// Scratch (allocation-free rule: __device__ globals).
__device__ float g_q [NB*NH*NT*NHD];   // [B,H,T,HD]
__device__ float g_kt[NB*NH*NHD*NT];   // [B,H,HD,T]  (K projected + transposed)
__device__ float g_v [NB*NH*NT*NHD];   // [B,H,T,HD]
__device__ float g_o [NB*NH*NT*NHD];   // [B,H,T,HD] attention output
// Fragment-ordered tf32 weights: [mat(4)][bn_idx(8)][stage(64)][2048 u32] = 16 MB.
__device__ unsigned g_wf[4 * 8 * 64 * 2048];

__device__ __forceinline__ unsigned f2tf(float f) {
    unsigned u;
    asm("cvt.rna.tf32.f32 %0, %1;" : "=r"(u) : "f"(f));
    return u;
}
__device__ __forceinline__ float tf32r(float f) { return __uint_as_float(f2tf(f)); }

__device__ __forceinline__ void mma_tf32(float c[4], const unsigned a[4], const unsigned b[2]) {
    asm volatile(
        "mma.sync.aligned.m16n8k8.row.col.f32.tf32.tf32.f32 "
        "{%0,%1,%2,%3}, {%4,%5,%6,%7}, {%8,%9}, {%0,%1,%2,%3};"
        : "+f"(c[0]), "+f"(c[1]), "+f"(c[2]), "+f"(c[3])
        : "r"(a[0]), "r"(a[1]), "r"(a[2]), "r"(a[3]), "r"(b[0]), "r"(b[1]));
}
__device__ __forceinline__ void mma_f(float c[4], const float a[4], const float b0, const float b1) {
    asm volatile(
        "mma.sync.aligned.m16n8k8.row.col.f32.tf32.tf32.f32 "
        "{%0,%1,%2,%3}, {%4,%5,%6,%7}, {%8,%9}, {%0,%1,%2,%3};"
        : "+f"(c[0]), "+f"(c[1]), "+f"(c[2]), "+f"(c[3])
        : "r"(__float_as_uint(a[0])), "r"(__float_as_uint(a[1])),
          "r"(__float_as_uint(a[2])), "r"(__float_as_uint(a[3])),
          "r"(__float_as_uint(b0)),   "r"(__float_as_uint(b1)));
}

// ---------------------------------------------------------------------------
// Weight prepass: convert W[N=1024,K=1024] row-major fp32 into tf32 fragment
// order. Frag layout per (bn_idx, stage): 2048 u32; addr =
//   tile(n8_tile = n>>3 within 128, kt = k8 within 16)*64 + lane*2 + reg,
//   lane = (n&7)*4 + (k&3), reg = (k>>2)&1  -- identical to smem layout.
// ---------------------------------------------------------------------------
__global__ void wconv(const float* __restrict__ Wq, const float* __restrict__ Wk,
                      const float* __restrict__ Wv, const float* __restrict__ Wo)
{
    int id = blockIdx.x * 256 + threadIdx.x;     // 0 .. 4*2^20-1
    int mat   = id >> 20;
    int rem   = id & 0xFFFFF;
    int bnidx = rem >> 17;
    int rem2  = rem & 0x1FFFF;
    int s     = rem2 >> 11;
    int off   = rem2 & 2047;

    int tile = off >> 6;          // 0..31
    int w    = off & 63;
    int reg  = w & 1;
    int lanef = w >> 1;           // 0..31
    int nsub = lanef >> 2;        // n & 7
    int ksub = lanef & 3;         // k & 3
    int nt2  = tile >> 1;         // (n within 128) >> 3
    int ktb  = tile & 1;          // (k within 16) >> 3

    int n = bnidx * 128 + nt2 * 8 + nsub;
    int k = s * 16 + ktb * 8 + reg * 4 + ksub;

    const float* W = (mat == 0) ? Wq : (mat == 1) ? Wk : (mat == 2) ? Wv : Wo;
    g_wf[id] = f2tf(W[(size_t)n * ND + k]);
}

// ---------------------------------------------------------------------------
// GEMM core, K-tile 16, 2 CTAs/SM. A staged with rotated scalar stores
// (2-way conflicts); W staged as a pure vector copy from g_wf (no cvt,
// coalesced LDG.128, conflict-free STS.128). Results bit-identical to R16.
// ---------------------------------------------------------------------------
struct GemmCore {
    unsigned* As;   // 2 bufs x 2048 u32
    unsigned* Ws;   // 2 bufs x 2048 u32
    int tid, lane, wm, wn, bm, bn;
    float acc[4][4][4];
    float4 ar[2];
    uint4 wu[2];

    __device__ __forceinline__ void init(unsigned* sh, int bm_, int bn_) {
        As = sh; Ws = sh + 4096;
        tid = threadIdx.x; lane = tid & 31;
        int warp = tid >> 5;
        wm = warp & 1; wn = warp >> 1;
        bm = bm_; bn = bn_;
#pragma unroll
        for (int mi = 0; mi < 4; mi++)
#pragma unroll
            for (int nj = 0; nj < 4; nj++)
#pragma unroll
                for (int r = 0; r < 4; r++) acc[mi][nj][r] = 0.f;
    }

    template<int AMODE>
    __device__ __forceinline__ void ldg(const float* __restrict__ A,
                                        const unsigned* __restrict__ Wfrag, int s) {
#pragma unroll
        for (int l = 0; l < 2; l++) {
            int idx = l * 256 + tid;
            int row = idx >> 2;          // 0..127
            int kq  = idx & 3;           // float4 within 16-wide k stage
            int kg  = s * 16 + kq * 4;
            if (AMODE == 0) {
                ar[l] = *(const float4*)(A + (size_t)(bm + row) * ND + kg);
            } else {
                int m  = bm + row;
                int b_ = m >> 11, t_ = m & (NT - 1);
                int h_ = kg >> 6, hd = kg & 63;
                ar[l] = *(const float4*)(A + (((size_t)(b_ * NH + h_) * NT + t_) * NHD + hd));
            }
        }
        const uint4* wf = (const uint4*)(Wfrag + (size_t)s * 2048);
        wu[0] = wf[tid];
        wu[1] = wf[tid + 256];
    }

    __device__ __forceinline__ void sts(int buf) {
        unsigned* ab = As + buf * 2048;
#pragma unroll
        for (int l = 0; l < 2; l++) {
            int idx = l * 256 + tid;
            int row = idx >> 2;
            int kq  = idx & 3;
            float ae[4] = {ar[l].x, ar[l].y, ar[l].z, ar[l].w};
            unsigned* p = ab + (((row >> 4) * 2 + (kq >> 1)) << 7);
            int reg = ((kq & 1) << 1) + ((row >> 3) & 1);
            int lb  = (row & 7) * 4;
            int rotA = (row >> 1) & 3;
#pragma unroll
            for (int e = 0; e < 4; e++) {
                int ee = (e + rotA) & 3;
                p[(lb + ee) * 4 + reg] = f2tf(ae[ee]);
            }
        }
        uint4* wb4 = (uint4*)(Ws + buf * 2048);
        wb4[tid]       = wu[0];
        wb4[tid + 256] = wu[1];
    }

    __device__ __forceinline__ void compute(int buf) {
        const unsigned* ab = As + buf * 2048;
        const unsigned* wb = Ws + buf * 2048;
#pragma unroll
        for (int kt = 0; kt < 2; kt++) {
            unsigned af[4][4];
#pragma unroll
            for (int mi = 0; mi < 4; mi++) {
                uint4 t = *(const uint4*)(ab + ((((wm * 4 + mi) * 2 + kt)) << 7) + (lane << 2));
                af[mi][0] = t.x; af[mi][1] = t.y; af[mi][2] = t.z; af[mi][3] = t.w;
            }
            unsigned bf[4][2];
#pragma unroll
            for (int nj = 0; nj < 4; nj++) {
                uint2 t = *(const uint2*)(wb + ((((wn * 4 + nj) * 2 + kt)) << 6) + (lane << 1));
                bf[nj][0] = t.x; bf[nj][1] = t.y;
            }
#pragma unroll
            for (int mi = 0; mi < 4; mi++)
#pragma unroll
                for (int nj = 0; nj < 4; nj++)
                    mma_tf32(acc[mi][nj], af[mi], bf[nj]);
        }
    }

    // OMODE: 0 -> [B,H,T,HD]; 1 -> [B,H,HD,T]; 2 -> row-major [M,N]
    template<int OMODE>
    __device__ __forceinline__ void epilogue(const float* __restrict__ bias,
                                             float* __restrict__ Cout) {
#pragma unroll
        for (int nj = 0; nj < 4; nj++) {
            int col = bn + (wn * 4 + nj) * 8 + (lane & 3) * 2;
            float b0 = bias[col], b1 = bias[col + 1];
#pragma unroll
            for (int mi = 0; mi < 4; mi++) {
                int row = bm + (wm * 4 + mi) * 16 + (lane >> 2);
                float v00 = acc[mi][nj][0] + b0, v01 = acc[mi][nj][1] + b1;
                float v10 = acc[mi][nj][2] + b0, v11 = acc[mi][nj][3] + b1;
                if (OMODE == 2) {
                    *(float2*)(Cout + (size_t)row * ND + col)       = make_float2(v00, v01);
                    *(float2*)(Cout + (size_t)(row + 8) * ND + col) = make_float2(v10, v11);
                } else if (OMODE == 0) {
                    int b_ = row >> 11, t_ = row & (NT - 1);
                    int h_ = col >> 6, hd = col & 63;
                    float* p = Cout + (((size_t)(b_ * NH + h_) * NT + t_) * NHD + hd);
                    *(float2*)p             = make_float2(v00, v01);
                    *(float2*)(p + 8 * NHD) = make_float2(v10, v11);
                } else { // OMODE 1: [B,H,HD,T]
                    int b_ = row >> 11, t_ = row & (NT - 1);
                    int h_ = col >> 6, hd = col & 63;
                    float* p = Cout + (((size_t)(b_ * NH + h_) * NHD + hd) * NT + t_);
                    p[0]      = v00;
                    p[NT]     = v01;
                    p[8]      = v10;
                    p[NT + 8] = v11;
                }
            }
        }
    }
};

template<int AMODE>
__device__ __forceinline__ void gemm_body(GemmCore& gc, const float* A,
                                          const unsigned* Wfrag) {
    gc.ldg<AMODE>(A, Wfrag, 0);
    gc.sts(0);
    __syncthreads();
    for (int s = 0; s < 64; s++) {
        int buf = s & 1;
        if (s < 63) gc.ldg<AMODE>(A, Wfrag, s + 1);
        gc.compute(buf);
        if (s < 63) gc.sts(buf ^ 1);
        __syncthreads();
    }
}

// Fused Q/K/V projection: grid (24, 64); blockIdx.x = which*8 + bn_idx.
__global__ __launch_bounds__(256, 2)
void gemm_qkv(const float* __restrict__ qin, const float* __restrict__ kin,
              const float* __restrict__ vin,
              const float* __restrict__ bq, const float* __restrict__ bk,
              const float* __restrict__ bv,
              float* __restrict__ oq, float* __restrict__ okt, float* __restrict__ ov)
{
    extern __shared__ unsigned sh[];
    const int which = blockIdx.x >> 3;
    const int bnidx = blockIdx.x & 7;
    const int bn = bnidx * 128;
    const int bm = blockIdx.y * 128;
    const unsigned* Wfrag = g_wf + ((size_t)(which * 8 + bnidx) * 64) * 2048;

    GemmCore gc;
    gc.init(sh, bm, bn);
    if (which == 0) {
        gemm_body<0>(gc, qin, Wfrag);
        gc.epilogue<0>(bq, oq);
    } else if (which == 1) {
        gemm_body<0>(gc, kin, Wfrag);
        gc.epilogue<1>(bk, okt);     // K proj + transpose fused
    } else {
        gemm_body<0>(gc, vin, Wfrag);
        gc.epilogue<0>(bv, ov);
    }
}

// Output projection: A gathered from head layout, row-major out. Wo = mat 3.
__global__ __launch_bounds__(256, 2)
void gemm_out(const float* __restrict__ A, const float* __restrict__ bias,
              float* __restrict__ Cout)
{
    extern __shared__ unsigned sh[];
    const unsigned* Wfrag = g_wf + ((size_t)(3 * 8 + blockIdx.x) * 64) * 2048;
    GemmCore gc;
    gc.init(sh, blockIdx.y * 128, blockIdx.x * 128);
    gemm_body<1>(gc, A, Wfrag);
    gc.epilogue<2>(bias, Cout);
}

// ---------------------------------------------------------------------------
// Flash attention v10 (unchanged from passing R16): single-chain tf32 S,
// rotated staging. 256 threads = 8 warps; CTA = 128 queries.
// smem (u32), 64 KB -> 2 CTAs/SM:
//  QH [0,8192)      tile(mt*8+kt)*128: uint4/lane = A-frag
//  KH [8192,12288)  tile(nt*8+kt)*64 : uint2/lane
//  VH [12288,16384) tile(nt*8+kt)*64 : uint2/lane
// ---------------------------------------------------------------------------
__global__ __launch_bounds__(256, 2)
void attn_mma(const float* __restrict__ qp, const float* __restrict__ ktp,
              const float* __restrict__ vp, float* __restrict__ ao)
{
    extern __shared__ unsigned smu[];

    const int tid  = threadIdx.x;
    const int lane = tid & 31;
    const int warp = tid >> 5;
    const int r    = lane >> 2;          // 0..7
    const int g    = lane & 3;           // 0..3
    const int bh   = blockIdx.y;
    const int q0   = blockIdx.x * 128;

    const float* qb = qp  + ((size_t)bh * NT + q0) * NHD;
    const float* kb = ktp + (size_t)bh * NHD * NT;
    const float* vb = vp  + (size_t)bh * NT * NHD;

    // ---- Stage Q once in A-frag order (hi only), rotated stores. ----
#pragma unroll
    for (int i = 0; i < 8; i++) {
        int idx = i * 256 + tid;
        int uu = idx & 31, blk = idx >> 5;
        int qrow = (uu >> 2) + (blk & 15) * 8;      // 0..127
        int f4   = (uu & 3) + (blk >> 4) * 4;       // 0..15
        float4 x = *(const float4*)(qb + qrow * NHD + f4 * 4);
        float xe[4] = {x.x, x.y, x.z, x.w};
        int mt = qrow >> 4;
        int lb = (qrow & 7) * 4;
        int rr = (qrow >> 3) & 1;
        int rot = (qrow >> 1) & 3;
#pragma unroll
        for (int e = 0; e < 4; e++) {
            int ee = (e + rot) & 3;
            int hd = f4 * 4 + ee;
            int ad = ((mt * 8 + (hd >> 3)) * 128) + (lb + (hd & 3)) * 4
                     + ((hd >> 2) & 1) * 2 + rr;
            smu[ad] = f2tf(xe[ee]);
        }
    }

    float o[8][4];
#pragma unroll
    for (int nt = 0; nt < 8; nt++)
#pragma unroll
        for (int c = 0; c < 4; c++) o[nt][c] = 0.f;
    float m0 = -1e30f, m1 = -1e30f, l0 = 0.f, l1 = 0.f;

    for (int t0 = 0; t0 < NT; t0 += 64) {
        __syncthreads();   // prev compute done before restaging (covers Q on iter 0)
        // ---- Stage K and V (hi only) in B-frag order, rotated stores. ----
#pragma unroll
        for (int i = 0; i < 4; i++) {
            int idx = i * 256 + tid;
            int uu = idx & 31, blk = idx >> 5;      // 0..31
            int row = (uu >> 2) + (blk & 7) * 8;    // 0..63
            int f4  = (uu & 3) + (blk >> 3) * 4;    // 0..15
            int rot = uu & 3;
            {   // K: row = hd, f4 indexes keys
                float4 x = *(const float4*)(kb + (size_t)row * NT + t0 + f4 * 4);
                float xe[4] = {x.x, x.y, x.z, x.w};
                int kt = row >> 3;
                int reg = (row >> 2) & 1;
                int lh = row & 3;
#pragma unroll
                for (int e = 0; e < 4; e++) {
                    int ee = (e + rot) & 3;
                    int key = f4 * 4 + ee;
                    int ad = 8192 + (((key >> 3) * 8 + kt) * 64)
                             + ((key & 7) * 4 + lh) * 2 + reg;
                    smu[ad] = f2tf(xe[ee]);
                }
            }
            {   // V: row = key, f4 indexes hd
                float4 y = *(const float4*)(vb + (size_t)(t0 + row) * NHD + f4 * 4);
                float ye[4] = {y.x, y.y, y.z, y.w};
                int kt = row >> 3;
                int reg = (row >> 2) & 1;
                int lk = row & 3;
#pragma unroll
                for (int e = 0; e < 4; e++) {
                    int ee = (e + rot) & 3;
                    int hd = f4 * 4 + ee;
                    int ad = 12288 + (((hd >> 3) * 8 + kt) * 64)
                             + ((hd & 7) * 4 + lk) * 2 + reg;
                    smu[ad] = f2tf(ye[ee]);
                }
            }
        }
        __syncthreads();

        // ---- S = Q K^T : single chain (pure tf32) ----
        float s[8][4];
#pragma unroll
        for (int nt = 0; nt < 8; nt++)
#pragma unroll
            for (int c = 0; c < 4; c++) s[nt][c] = 0.f;

#pragma unroll
        for (int kt = 0; kt < 8; kt++) {
            uint4 qh4 = *(const uint4*)(smu + (warp * 8 + kt) * 128 + lane * 4);
            float ah[4] = {__uint_as_float(qh4.x), __uint_as_float(qh4.y),
                           __uint_as_float(qh4.z), __uint_as_float(qh4.w)};
#pragma unroll
            for (int half = 0; half < 2; half++) {
                uint2 kk[4];
#pragma unroll
                for (int j = 0; j < 4; j++)
                    kk[j] = *(const uint2*)(smu + 8192
                              + (((half * 4 + j) * 8 + kt) * 64) + lane * 2);
#pragma unroll
                for (int j = 0; j < 4; j++)
                    mma_f(s[half*4+j], ah, __uint_as_float(kk[j].x), __uint_as_float(kk[j].y));
            }
        }

        // ---- online softmax (rows r, r+8; quad-wide reductions) ----
        float mx0 = -1e30f, mx1 = -1e30f;
#pragma unroll
        for (int nt = 0; nt < 8; nt++) {
            s[nt][0] *= 0.125f; s[nt][1] *= 0.125f;
            s[nt][2] *= 0.125f; s[nt][3] *= 0.125f;
            mx0 = fmaxf(mx0, fmaxf(s[nt][0], s[nt][1]));
            mx1 = fmaxf(mx1, fmaxf(s[nt][2], s[nt][3]));
        }
        mx0 = fmaxf(mx0, __shfl_xor_sync(0xffffffffu, mx0, 1));
        mx0 = fmaxf(mx0, __shfl_xor_sync(0xffffffffu, mx0, 2));
        mx1 = fmaxf(mx1, __shfl_xor_sync(0xffffffffu, mx1, 1));
        mx1 = fmaxf(mx1, __shfl_xor_sync(0xffffffffu, mx1, 2));

        float mn0 = fmaxf(m0, mx0), mn1 = fmaxf(m1, mx1);
        float c0 = __expf(m0 - mn0), c1 = __expf(m1 - mn1);
        m0 = mn0; m1 = mn1;

        float rs0 = 0.f, rs1 = 0.f;
#pragma unroll
        for (int nt = 0; nt < 8; nt++) {
            float p;
            p = tf32r(__expf(s[nt][0] - mn0)); s[nt][0] = p; rs0 += p;
            p = tf32r(__expf(s[nt][1] - mn0)); s[nt][1] = p; rs0 += p;
            p = tf32r(__expf(s[nt][2] - mn1)); s[nt][2] = p; rs1 += p;
            p = tf32r(__expf(s[nt][3] - mn1)); s[nt][3] = p; rs1 += p;
        }
        rs0 += __shfl_xor_sync(0xffffffffu, rs0, 1);
        rs0 += __shfl_xor_sync(0xffffffffu, rs0, 2);
        rs1 += __shfl_xor_sync(0xffffffffu, rs1, 1);
        rs1 += __shfl_xor_sync(0xffffffffu, rs1, 2);
        l0 = l0 * c0 + rs0;
        l1 = l1 * c1 + rs1;
#pragma unroll
        for (int nt = 0; nt < 8; nt++) {
            o[nt][0] *= c0; o[nt][1] *= c0;
            o[nt][2] *= c1; o[nt][3] *= c1;
        }

        // ---- O += P V : P C-frag -> A-frag via quad shuffles; LDS.64 V frags ----
        const int src1 = (lane & ~3) | (g >> 1);
        const int src2 = src1 + 2;
        const bool odd = (g & 1) != 0;
#pragma unroll
        for (int kt = 0; kt < 8; kt++) {
            float x0 = __shfl_sync(0xffffffffu, s[kt][0], src1);
            float x1 = __shfl_sync(0xffffffffu, s[kt][1], src1);
            float y0 = __shfl_sync(0xffffffffu, s[kt][2], src1);
            float y1 = __shfl_sync(0xffffffffu, s[kt][3], src1);
            float z0 = __shfl_sync(0xffffffffu, s[kt][0], src2);
            float z1 = __shfl_sync(0xffffffffu, s[kt][1], src2);
            float w0 = __shfl_sync(0xffffffffu, s[kt][2], src2);
            float w1 = __shfl_sync(0xffffffffu, s[kt][3], src2);
            float a[4];
            a[0] = odd ? x1 : x0;
            a[1] = odd ? y1 : y0;
            a[2] = odd ? z1 : z0;
            a[3] = odd ? w1 : w0;

#pragma unroll
            for (int nt = 0; nt < 8; nt++) {
                uint2 vv = *(const uint2*)(smu + 12288 + ((nt * 8 + kt) * 64) + lane * 2);
                mma_f(o[nt], a, __uint_as_float(vv.x), __uint_as_float(vv.y));
            }
        }
    }

    // ---- normalize + store [B,H,T,HD] ----
    float inv0 = 1.f / l0, inv1 = 1.f / l1;
    float* ob = ao + ((size_t)bh * NT + q0 + warp * 16) * NHD;
#pragma unroll
    for (int nt = 0; nt < 8; nt++) {
        int col = nt * 8 + 2 * g;
        *(float2*)(ob + (size_t)r * NHD + col) =
            make_float2(o[nt][0] * inv0, o[nt][1] * inv0);
        *(float2*)(ob + (size_t)(r + 8) * NHD + col) =
            make_float2(o[nt][2] * inv1, o[nt][3] * inv1);
    }
}

// ---------------------------------------------------------------------------
extern "C" void kernel_launch(void* const* d_in, const int* in_sizes, int n_in,
                              void* d_out, int out_size)
{
    const float* q  = (const float*)d_in[0];
    const float* k  = (const float*)d_in[1];
    const float* v  = (const float*)d_in[2];
    const float* Wq = (const float*)d_in[3];
    const float* bq = (const float*)d_in[4];
    const float* Wk = (const float*)d_in[5];
    const float* bk = (const float*)d_in[6];
    const float* Wv = (const float*)d_in[7];
    const float* bv = (const float*)d_in[8];
    const float* Wo = (const float*)d_in[9];
    const float* bo = (const float*)d_in[10];
    float* out = (float*)d_out;

    float *pq, *pkt, *pv, *po;
    cudaGetSymbolAddress((void**)&pq,  g_q);
    cudaGetSymbolAddress((void**)&pkt, g_kt);
    cudaGetSymbolAddress((void**)&pv,  g_v);
    cudaGetSymbolAddress((void**)&po,  g_o);

    const int gemm_smem = 32768;   // 2 x (8KB A + 8KB W)
    cudaFuncSetAttribute(gemm_qkv, cudaFuncAttributeMaxDynamicSharedMemorySize, gemm_smem);
    cudaFuncSetAttribute(gemm_out, cudaFuncAttributeMaxDynamicSharedMemorySize, gemm_smem);

    // Weight prepass: 4 * 2^20 u32 -> 16384 blocks of 256.
    wconv<<<16384, 256>>>(Wq, Wk, Wv, Wo);

    // One fused launch for all three input projections (1536 CTAs).
    gemm_qkv<<<dim3(24, 64), 256, gemm_smem>>>(q, k, v, bq, bk, bv, pq, pkt, pv);

    const int attn_smem = 16384 * 4;   // 65,536 B -> 2 CTAs/SM
    cudaFuncSetAttribute(attn_mma, cudaFuncAttributeMaxDynamicSharedMemorySize, attn_smem);
    attn_mma<<<dim3(NT / 128, NB * NH), 256, attn_smem>>>(pq, pkt, pv, po);

    gemm_out<<<dim3(8, 64), 256, gemm_smem>>>(po, bo, out);
}